// round 10
// baseline (speedup 1.0000x reference)
#include <cuda_runtime.h>
#include <cuda_fp16.h>
#include <cuda_bf16.h>
#include <cstdint>

#define NMAX 100000
#define EMAX 1600000
#define IN_F 256
#define HID 128
#define OUT_F 64
#define SCAN_B 1024

// ---------------------------------------------------------------------------
// Scratch (bss, no runtime allocation)
// ---------------------------------------------------------------------------
__device__ int   g_cnt[NMAX];
__device__ int   g_scan[NMAX];
__device__ int   g_bsum[(NMAX + SCAN_B - 1) / SCAN_B];
__device__ int   g_rowptr[NMAX + 1];
__device__ int   g_cursor[NMAX];
__device__ __align__(16) int2  g_csr[EMAX];        // {src, coef-bits}
__device__ float g_dinv[NMAX];
__device__ __align__(128) __half g_h1[(size_t)NMAX * HID];    // fp16 h1
__device__ __align__(128) __half g_agg1[(size_t)NMAX * HID];  // fp16 relu(agg+b1)
__device__ __align__(128) __half g_h2[(size_t)NMAX * OUT_F];  // fp16 h2
__device__ __align__(128) __half g_w1t[HID * IN_F];   // fp16 W1^T
__device__ __align__(128) __half g_w2t[OUT_F * HID];  // fp16 W2^T

// ---------------------------------------------------------------------------
// PTX helpers (baseline PTX only)
// ---------------------------------------------------------------------------
__device__ __forceinline__ uint32_t smem_u32(const void* p) {
    uint32_t a;
    asm("{ .reg .u64 t; cvta.to.shared.u64 t, %1; cvt.u32.u64 %0, t; }"
        : "=r"(a) : "l"(p));
    return a;
}
__device__ __forceinline__ void cp_async16(uint32_t sa, const void* g) {
    asm volatile("cp.async.cg.shared.global [%0], [%1], 16;" ::"r"(sa), "l"(g));
}
__device__ __forceinline__ void cp_commit() {
    asm volatile("cp.async.commit_group;");
}
template <int N>
__device__ __forceinline__ void cp_wait() {
    asm volatile("cp.async.wait_group %0;" ::"n"(N));
}
__device__ __forceinline__ void ldsm_x4(uint32_t& r0, uint32_t& r1, uint32_t& r2,
                                        uint32_t& r3, uint32_t addr) {
    asm volatile("ldmatrix.sync.aligned.m8n8.x4.shared.b16 {%0,%1,%2,%3}, [%4];"
                 : "=r"(r0), "=r"(r1), "=r"(r2), "=r"(r3) : "r"(addr));
}
__device__ __forceinline__ void ldsm_x2(uint32_t& r0, uint32_t& r1, uint32_t addr) {
    asm volatile("ldmatrix.sync.aligned.m8n8.x2.shared.b16 {%0,%1}, [%2];"
                 : "=r"(r0), "=r"(r1) : "r"(addr));
}
__device__ __forceinline__ float2 lds64(uint32_t addr) {
    float2 v;
    asm volatile("ld.shared.v2.f32 {%0,%1}, [%2];"
                 : "=f"(v.x), "=f"(v.y) : "r"(addr));
    return v;
}
__device__ __forceinline__ uint32_t pack_h2(float lo, float hi) {
    __half2 h = __floats2half2_rn(lo, hi);
    return *reinterpret_cast<uint32_t*>(&h);
}
__device__ __forceinline__ void mma_f16(float* c, const uint32_t* a,
                                        const uint32_t* b) {
    asm volatile(
        "mma.sync.aligned.m16n8k16.row.col.f32.f16.f16.f32 "
        "{%0,%1,%2,%3}, {%4,%5,%6,%7}, {%8,%9}, {%0,%1,%2,%3};"
        : "+f"(c[0]), "+f"(c[1]), "+f"(c[2]), "+f"(c[3])
        : "r"(a[0]), "r"(a[1]), "r"(a[2]), "r"(a[3]), "r"(b[0]), "r"(b[1]));
}

// ---------------------------------------------------------------------------
// GEMM1: A fp32 in smem -> fp16 frags via LDS.64+cvt. B plain fp16.
// Block tile 128 x NT, BK = 16, 3-stage cp.async, fp32 accum, fp16 out.
// ---------------------------------------------------------------------------
template <int NT, int KT>
__global__ void __launch_bounds__(256)
k_gemm_f32a(int M, const float* __restrict__ A, const __half* __restrict__ BT,
            __half* __restrict__ C) {
    constexpr int BK = 16;
    constexpr int T = KT / BK;
    constexpr int A_STR = 96;
    constexpr int B_STR = 48;
    constexpr int A_ST = 128 * A_STR;
    constexpr int B_ST = NT * B_STR;
    constexpr int STAGE = A_ST + B_ST;
    constexpr int NFRAG = NT / 16;

    extern __shared__ __align__(16) char smem[];
    const uint32_t sb = smem_u32(smem);
    const int tid = threadIdx.x;
    const int wid = tid >> 5, lane = tid & 31;
    const int warpM = wid >> 1, warpN = wid & 1;
    const int brow = blockIdx.x * 128;

    float acc[2][NFRAG][4];
#pragma unroll
    for (int i = 0; i < 2; i++)
#pragma unroll
        for (int j = 0; j < NFRAG; j++)
#pragma unroll
            for (int q = 0; q < 4; q++) acc[i][j][q] = 0.f;

    auto prefetch = [&](int t, int s) {
        const uint32_t ao = sb + s * STAGE;
        const uint32_t bo = ao + A_ST;
#pragma unroll
        for (int i = tid; i < 128 * 4; i += 256) {
            int m = i >> 2, q = i & 3;
            int gr = brow + m;
            if (gr >= M) gr = M - 1;
            cp_async16(ao + m * A_STR + q * 16,
                       A + (size_t)gr * KT + t * BK + q * 4);
        }
#pragma unroll
        for (int i = tid; i < NT * 2; i += 256) {
            int r = i >> 1, q = i & 1;
            cp_async16(bo + r * B_STR + q * 16,
                       BT + (size_t)r * KT + t * BK + q * 8);
        }
        cp_commit();
    };

    prefetch(0, 0);
    if (T > 1) prefetch(1, 1);

    const int ti = lane >> 3, ri = lane & 7;
    const int r4 = lane >> 2, c4 = lane & 3;

    for (int t = 0; t < T; t++) {
        const int s = t % 3;
        if (t + 1 < T) cp_wait<1>(); else cp_wait<0>();
        __syncthreads();
        if (t + 2 < T) prefetch(t + 2, (t + 2) % 3);

        const uint32_t ao = sb + s * STAGE;
        const uint32_t bo = ao + A_ST;

        uint32_t af[2][4];
#pragma unroll
        for (int mf = 0; mf < 2; mf++) {
            int m0 = warpM * 32 + mf * 16 + r4;
            uint32_t b0 = ao + m0 * A_STR + c4 * 8;
            uint32_t b1 = ao + (m0 + 8) * A_STR + c4 * 8;
            float2 f00 = lds64(b0);
            float2 f10 = lds64(b1);
            float2 f01 = lds64(b0 + 32);
            float2 f11 = lds64(b1 + 32);
            af[mf][0] = pack_h2(f00.x, f00.y);
            af[mf][1] = pack_h2(f10.x, f10.y);
            af[mf][2] = pack_h2(f01.x, f01.y);
            af[mf][3] = pack_h2(f11.x, f11.y);
        }
        uint32_t bf[NFRAG][2];
#pragma unroll
        for (int fp = 0; fp < NFRAG / 2; fp++) {
            int nr = warpN * (NT / 2) + fp * 16 + (ti >> 1) * 8 + ri;
            uint32_t off = nr * B_STR + (ti & 1) * 16;
            ldsm_x4(bf[2 * fp][0], bf[2 * fp][1], bf[2 * fp + 1][0],
                    bf[2 * fp + 1][1], bo + off);
        }
#pragma unroll
        for (int mf = 0; mf < 2; mf++)
#pragma unroll
            for (int nf = 0; nf < NFRAG; nf++)
                mma_f16(acc[mf][nf], af[mf], bf[nf]);
    }

#pragma unroll
    for (int mf = 0; mf < 2; mf++) {
        int row0 = brow + warpM * 32 + mf * 16 + (lane >> 2);
        int row1 = row0 + 8;
#pragma unroll
        for (int nf = 0; nf < NFRAG; nf++) {
            int col = warpN * (NT / 2) + nf * 8 + (lane & 3) * 2;
            if (row0 < M)
                *reinterpret_cast<__half2*>(C + (size_t)row0 * NT + col) =
                    __floats2half2_rn(acc[mf][nf][0], acc[mf][nf][1]);
            if (row1 < M)
                *reinterpret_cast<__half2*>(C + (size_t)row1 * NT + col) =
                    __floats2half2_rn(acc[mf][nf][2], acc[mf][nf][3]);
        }
    }
}

// ---------------------------------------------------------------------------
// GEMM2: A fp16 (agg1), B plain fp16.
// ---------------------------------------------------------------------------
template <int NT, int KT>
__global__ void __launch_bounds__(256)
k_gemm_f16a(int M, const __half* __restrict__ A, const __half* __restrict__ BT,
            __half* __restrict__ C) {
    constexpr int BK = 16;
    constexpr int T = KT / BK;
    constexpr int STR = 48;
    constexpr int A_ST = 128 * STR;
    constexpr int B_ST = NT * STR;
    constexpr int STAGE = A_ST + B_ST;
    constexpr int NFRAG = NT / 16;

    extern __shared__ __align__(16) char smem[];
    const uint32_t sb = smem_u32(smem);
    const int tid = threadIdx.x;
    const int wid = tid >> 5, lane = tid & 31;
    const int warpM = wid >> 1, warpN = wid & 1;
    const int brow = blockIdx.x * 128;

    float acc[2][NFRAG][4];
#pragma unroll
    for (int i = 0; i < 2; i++)
#pragma unroll
        for (int j = 0; j < NFRAG; j++)
#pragma unroll
            for (int q = 0; q < 4; q++) acc[i][j][q] = 0.f;

    auto prefetch = [&](int t, int s) {
        const uint32_t ao = sb + s * STAGE;
        const uint32_t bo = ao + A_ST;
#pragma unroll
        for (int i = tid; i < 128 * 2; i += 256) {
            int m = i >> 1, q = i & 1;
            int gr = brow + m;
            if (gr >= M) gr = M - 1;
            cp_async16(ao + m * STR + q * 16,
                       A + (size_t)gr * KT + t * BK + q * 8);
        }
#pragma unroll
        for (int i = tid; i < NT * 2; i += 256) {
            int r = i >> 1, q = i & 1;
            cp_async16(bo + r * STR + q * 16,
                       BT + (size_t)r * KT + t * BK + q * 8);
        }
        cp_commit();
    };

    prefetch(0, 0);
    if (T > 1) prefetch(1, 1);

    const int ti = lane >> 3, ri = lane & 7;

    for (int t = 0; t < T; t++) {
        const int s = t % 3;
        if (t + 1 < T) cp_wait<1>(); else cp_wait<0>();
        __syncthreads();
        if (t + 2 < T) prefetch(t + 2, (t + 2) % 3);

        const uint32_t ao = sb + s * STAGE;
        const uint32_t bo = ao + A_ST;

        uint32_t af[2][4];
#pragma unroll
        for (int mf = 0; mf < 2; mf++) {
            int m = warpM * 32 + mf * 16 + (ti & 1) * 8 + ri;
            uint32_t addr = ao + m * STR + (ti >> 1) * 16;
            ldsm_x4(af[mf][0], af[mf][1], af[mf][2], af[mf][3], addr);
        }
        uint32_t bf[NFRAG][2];
#pragma unroll
        for (int fp = 0; fp < NFRAG / 2; fp++) {
            int nr = warpN * (NT / 2) + fp * 16 + (ti >> 1) * 8 + ri;
            uint32_t off = nr * STR + (ti & 1) * 16;
            ldsm_x4(bf[2 * fp][0], bf[2 * fp][1], bf[2 * fp + 1][0],
                    bf[2 * fp + 1][1], bo + off);
        }
#pragma unroll
        for (int mf = 0; mf < 2; mf++)
#pragma unroll
            for (int nf = 0; nf < NFRAG; nf++)
                mma_f16(acc[mf][nf], af[mf], bf[nf]);
    }

#pragma unroll
    for (int mf = 0; mf < 2; mf++) {
        int row0 = brow + warpM * 32 + mf * 16 + (lane >> 2);
        int row1 = row0 + 8;
#pragma unroll
        for (int nf = 0; nf < NFRAG; nf++) {
            int col = warpN * (NT / 2) + nf * 8 + (lane & 3) * 2;
            if (row0 < M)
                *reinterpret_cast<__half2*>(C + (size_t)row0 * NT + col) =
                    __floats2half2_rn(acc[mf][nf][0], acc[mf][nf][1]);
            if (row1 < M)
                *reinterpret_cast<__half2*>(C + (size_t)row1 * NT + col) =
                    __floats2half2_rn(acc[mf][nf][2], acc[mf][nf][3]);
        }
    }
}

// ---------------------------------------------------------------------------
// Weight transpose -> fp16
// ---------------------------------------------------------------------------
__global__ void k_transpose_h(const float* __restrict__ W,
                              __half* __restrict__ WT, int K, int N) {
    int i = blockIdx.x * blockDim.x + threadIdx.x;
    if (i >= K * N) return;
    int k = i / N, nn = i % N;
    WT[(size_t)nn * K + k] = __float2half_rn(W[i]);
}

// ---------------------------------------------------------------------------
// CSR build (side stream)
// ---------------------------------------------------------------------------
__global__ void k_cnt(const int* __restrict__ dst, int* cnt, int e) {
    int i = blockIdx.x * blockDim.x + threadIdx.x;
    int base = i * 4;
    if (base + 3 < e) {
        int4 d = *reinterpret_cast<const int4*>(dst + base);
        atomicAdd(&cnt[d.x], 1);
        atomicAdd(&cnt[d.y], 1);
        atomicAdd(&cnt[d.z], 1);
        atomicAdd(&cnt[d.w], 1);
    } else {
        for (int j = base; j < e; j++) atomicAdd(&cnt[dst[j]], 1);
    }
}
__global__ void k_dinv(const int* __restrict__ cnt, float* dinv, int n) {
    int i = blockIdx.x * blockDim.x + threadIdx.x;
    if (i < n) dinv[i] = rsqrtf((float)(cnt[i] + 1));
}
__global__ void k_scan1(const int* __restrict__ cnt, int* scan, int* bsum, int n) {
    __shared__ int sh[SCAN_B];
    int i = blockIdx.x * SCAN_B + threadIdx.x;
    int v = (i < n) ? cnt[i] : 0;
    sh[threadIdx.x] = v;
    __syncthreads();
#pragma unroll
    for (int off = 1; off < SCAN_B; off <<= 1) {
        int t = (threadIdx.x >= off) ? sh[threadIdx.x - off] : 0;
        __syncthreads();
        sh[threadIdx.x] += t;
        __syncthreads();
    }
    if (i < n) scan[i] = sh[threadIdx.x];
    if (threadIdx.x == SCAN_B - 1) bsum[blockIdx.x] = sh[SCAN_B - 1];
}
__global__ void k_scan2(int* bsum, int nb) {
    __shared__ int sh[128];
    int v = (threadIdx.x < nb) ? bsum[threadIdx.x] : 0;
    sh[threadIdx.x] = v;
    __syncthreads();
#pragma unroll
    for (int off = 1; off < 128; off <<= 1) {
        int t = (threadIdx.x >= off) ? sh[threadIdx.x - off] : 0;
        __syncthreads();
        sh[threadIdx.x] += t;
        __syncthreads();
    }
    if (threadIdx.x < nb) bsum[threadIdx.x] = sh[threadIdx.x] - v;
}
__global__ void k_scan3(const int* __restrict__ cnt, const int* __restrict__ scan,
                        const int* __restrict__ bsum, int* rowptr, int* cursor, int n) {
    int i = blockIdx.x * blockDim.x + threadIdx.x;
    if (i >= n) return;
    int excl = scan[i] - cnt[i] + bsum[i / SCAN_B];
    rowptr[i] = excl;
    cursor[i] = excl;
    if (i == n - 1) rowptr[n] = excl + cnt[i];
}
__global__ void k_fill(const int* __restrict__ src, const int* __restrict__ dst,
                       const float* __restrict__ dinv, int* cursor,
                       int2* __restrict__ csr, int e) {
    int i = blockIdx.x * blockDim.x + threadIdx.x;
    int base = i * 4;
    if (base + 3 < e) {
        int4 sv = *reinterpret_cast<const int4*>(src + base);
        int4 dv = *reinterpret_cast<const int4*>(dst + base);
        const int ss[4] = {sv.x, sv.y, sv.z, sv.w};
        const int dd[4] = {dv.x, dv.y, dv.z, dv.w};
#pragma unroll
        for (int j = 0; j < 4; j++) {
            int pos = atomicAdd(&cursor[dd[j]], 1);
            csr[pos] = make_int2(ss[j],
                                 __float_as_int(dinv[ss[j]] * dinv[dd[j]]));
        }
    } else {
        for (int j = base; j < e; j++) {
            int s = src[j], d = dst[j];
            int pos = atomicAdd(&cursor[d], 1);
            csr[pos] = make_int2(s, __float_as_int(dinv[s] * dinv[d]));
        }
    }
}

// ---------------------------------------------------------------------------
// Warp-per-node aggregation (fp16 gathers), 4-edge unrolled.
// ---------------------------------------------------------------------------
__global__ void k_agg_csr128(const __half* __restrict__ h,
                             const int* __restrict__ rowptr,
                             const int2* __restrict__ csr,
                             const float* __restrict__ dinv,
                             const float* __restrict__ b1,
                             __half* __restrict__ out, int n) {
    int node = (blockIdx.x * blockDim.x + threadIdx.x) >> 5;
    int lane = threadIdx.x & 31;
    if (node >= n) return;
    float di = dinv[node];
    float c = di * di;
    uint2 raw = *reinterpret_cast<const uint2*>(h + (size_t)node * 128 + lane * 4);
    float2 p0 = __half22float2(*reinterpret_cast<const __half2*>(&raw.x));
    float2 p1 = __half22float2(*reinterpret_cast<const __half2*>(&raw.y));
    float4 acc = make_float4(p0.x * c, p0.y * c, p1.x * c, p1.y * c);
    int idx = rowptr[node], end = rowptr[node + 1];
#pragma unroll 1
    for (; idx + 3 < end; idx += 4) {
        int2 e0 = csr[idx], e1 = csr[idx + 1], e2 = csr[idx + 2], e3 = csr[idx + 3];
        uint2 r0 = *reinterpret_cast<const uint2*>(h + (size_t)e0.x * 128 + lane * 4);
        uint2 r1 = *reinterpret_cast<const uint2*>(h + (size_t)e1.x * 128 + lane * 4);
        uint2 r2 = *reinterpret_cast<const uint2*>(h + (size_t)e2.x * 128 + lane * 4);
        uint2 r3 = *reinterpret_cast<const uint2*>(h + (size_t)e3.x * 128 + lane * 4);
        float c0 = __int_as_float(e0.y), c1 = __int_as_float(e1.y);
        float c2 = __int_as_float(e2.y), c3 = __int_as_float(e3.y);
        {
            float2 a0 = __half22float2(*reinterpret_cast<const __half2*>(&r0.x));
            float2 a1 = __half22float2(*reinterpret_cast<const __half2*>(&r0.y));
            acc.x = fmaf(a0.x, c0, acc.x); acc.y = fmaf(a0.y, c0, acc.y);
            acc.z = fmaf(a1.x, c0, acc.z); acc.w = fmaf(a1.y, c0, acc.w);
        }
        {
            float2 a0 = __half22float2(*reinterpret_cast<const __half2*>(&r1.x));
            float2 a1 = __half22float2(*reinterpret_cast<const __half2*>(&r1.y));
            acc.x = fmaf(a0.x, c1, acc.x); acc.y = fmaf(a0.y, c1, acc.y);
            acc.z = fmaf(a1.x, c1, acc.z); acc.w = fmaf(a1.y, c1, acc.w);
        }
        {
            float2 a0 = __half22float2(*reinterpret_cast<const __half2*>(&r2.x));
            float2 a1 = __half22float2(*reinterpret_cast<const __half2*>(&r2.y));
            acc.x = fmaf(a0.x, c2, acc.x); acc.y = fmaf(a0.y, c2, acc.y);
            acc.z = fmaf(a1.x, c2, acc.z); acc.w = fmaf(a1.y, c2, acc.w);
        }
        {
            float2 a0 = __half22float2(*reinterpret_cast<const __half2*>(&r3.x));
            float2 a1 = __half22float2(*reinterpret_cast<const __half2*>(&r3.y));
            acc.x = fmaf(a0.x, c3, acc.x); acc.y = fmaf(a0.y, c3, acc.y);
            acc.z = fmaf(a1.x, c3, acc.z); acc.w = fmaf(a1.y, c3, acc.w);
        }
    }
#pragma unroll 1
    for (; idx < end; idx++) {
        int2 e0 = csr[idx];
        float c0 = __int_as_float(e0.y);
        uint2 r0 = *reinterpret_cast<const uint2*>(h + (size_t)e0.x * 128 + lane * 4);
        float2 a0 = __half22float2(*reinterpret_cast<const __half2*>(&r0.x));
        float2 a1 = __half22float2(*reinterpret_cast<const __half2*>(&r0.y));
        acc.x = fmaf(a0.x, c0, acc.x); acc.y = fmaf(a0.y, c0, acc.y);
        acc.z = fmaf(a1.x, c0, acc.z); acc.w = fmaf(a1.y, c0, acc.w);
    }
    float4 b = *reinterpret_cast<const float4*>(b1 + lane * 4);
    __half2 o0 = __floats2half2_rn(fmaxf(acc.x + b.x, 0.f), fmaxf(acc.y + b.y, 0.f));
    __half2 o1 = __floats2half2_rn(fmaxf(acc.z + b.z, 0.f), fmaxf(acc.w + b.w, 0.f));
    uint2 o;
    o.x = *reinterpret_cast<uint32_t*>(&o0);
    o.y = *reinterpret_cast<uint32_t*>(&o1);
    *reinterpret_cast<uint2*>(out + (size_t)node * 128 + lane * 4) = o;
}

__global__ void k_agg_csr64(const __half* __restrict__ h,
                            const int* __restrict__ rowptr,
                            const int2* __restrict__ csr,
                            const float* __restrict__ dinv,
                            const float* __restrict__ bias,
                            float* __restrict__ out, int n) {
    int node = (blockIdx.x * blockDim.x + threadIdx.x) >> 5;
    int lane = threadIdx.x & 31;
    if (node >= n) return;
    float di = dinv[node];
    float c = di * di;
    uint32_t raw = *reinterpret_cast<const uint32_t*>(h + (size_t)node * 64 + lane * 2);
    float2 v = __half22float2(*reinterpret_cast<const __half2*>(&raw));
    float2 acc = make_float2(v.x * c, v.y * c);
    int idx = rowptr[node], end = rowptr[node + 1];
#pragma unroll 1
    for (; idx + 3 < end; idx += 4) {
        int2 e0 = csr[idx], e1 = csr[idx + 1], e2 = csr[idx + 2], e3 = csr[idx + 3];
        uint32_t r0 = *reinterpret_cast<const uint32_t*>(h + (size_t)e0.x * 64 + lane * 2);
        uint32_t r1 = *reinterpret_cast<const uint32_t*>(h + (size_t)e1.x * 64 + lane * 2);
        uint32_t r2 = *reinterpret_cast<const uint32_t*>(h + (size_t)e2.x * 64 + lane * 2);
        uint32_t r3 = *reinterpret_cast<const uint32_t*>(h + (size_t)e3.x * 64 + lane * 2);
        float2 v0 = __half22float2(*reinterpret_cast<const __half2*>(&r0));
        float2 v1 = __half22float2(*reinterpret_cast<const __half2*>(&r1));
        float2 v2 = __half22float2(*reinterpret_cast<const __half2*>(&r2));
        float2 v3 = __half22float2(*reinterpret_cast<const __half2*>(&r3));
        acc.x = fmaf(v0.x, __int_as_float(e0.y), acc.x);
        acc.y = fmaf(v0.y, __int_as_float(e0.y), acc.y);
        acc.x = fmaf(v1.x, __int_as_float(e1.y), acc.x);
        acc.y = fmaf(v1.y, __int_as_float(e1.y), acc.y);
        acc.x = fmaf(v2.x, __int_as_float(e2.y), acc.x);
        acc.y = fmaf(v2.y, __int_as_float(e2.y), acc.y);
        acc.x = fmaf(v3.x, __int_as_float(e3.y), acc.x);
        acc.y = fmaf(v3.y, __int_as_float(e3.y), acc.y);
    }
#pragma unroll 1
    for (; idx < end; idx++) {
        int2 e0 = csr[idx];
        float c0 = __int_as_float(e0.y);
        uint32_t r0 = *reinterpret_cast<const uint32_t*>(h + (size_t)e0.x * 64 + lane * 2);
        float2 v0 = __half22float2(*reinterpret_cast<const __half2*>(&r0));
        acc.x = fmaf(v0.x, c0, acc.x); acc.y = fmaf(v0.y, c0, acc.y);
    }
    float2 b = *reinterpret_cast<const float2*>(bias + lane * 2);
    acc.x += b.x;
    acc.y += b.y;
    *reinterpret_cast<float2*>(out + (size_t)node * 64 + lane * 2) = acc;
}

// ---------------------------------------------------------------------------
// Launch
// ---------------------------------------------------------------------------
extern "C" void kernel_launch(void* const* d_in, const int* in_sizes, int n_in,
                              void* d_out, int out_size) {
    const float* x = (const float*)d_in[0];
    const int* ei = (const int*)d_in[1];
    const float* W1 = (const float*)d_in[2];
    const float* b1 = (const float*)d_in[3];
    const float* W2 = (const float*)d_in[4];
    const float* b2 = (const float*)d_in[5];
    float* out = (float*)d_out;

    const int n = in_sizes[0] / IN_F;  // 100000
    const int e = in_sizes[1] / 2;     // 1600000
    const int* src = ei;
    const int* dst = ei + e;
    const int nb = (n + SCAN_B - 1) / SCAN_B;

    int *p_cnt, *p_scan, *p_bsum, *p_rowptr, *p_cursor;
    int2* p_csr;
    float* p_dinv;
    __half *p_h1, *p_agg1, *p_h2, *p_w1t, *p_w2t;
    cudaGetSymbolAddress((void**)&p_cnt, g_cnt);
    cudaGetSymbolAddress((void**)&p_scan, g_scan);
    cudaGetSymbolAddress((void**)&p_bsum, g_bsum);
    cudaGetSymbolAddress((void**)&p_rowptr, g_rowptr);
    cudaGetSymbolAddress((void**)&p_cursor, g_cursor);
    cudaGetSymbolAddress((void**)&p_csr, g_csr);
    cudaGetSymbolAddress((void**)&p_dinv, g_dinv);
    cudaGetSymbolAddress((void**)&p_h1, g_h1);
    cudaGetSymbolAddress((void**)&p_agg1, g_agg1);
    cudaGetSymbolAddress((void**)&p_h2, g_h2);
    cudaGetSymbolAddress((void**)&p_w1t, g_w1t);
    cudaGetSymbolAddress((void**)&p_w2t, g_w2t);

    static cudaStream_t s2 = nullptr;
    static cudaEvent_t evFork = nullptr, evJoin = nullptr;
    if (s2 == nullptr) {
        cudaStreamCreateWithFlags(&s2, cudaStreamNonBlocking);
        cudaEventCreateWithFlags(&evFork, cudaEventDisableTiming);
        cudaEventCreateWithFlags(&evJoin, cudaEventDisableTiming);
    }

    // ---- fork: CSR build + W2 transpose on side stream
    cudaEventRecord(evFork, 0);
    cudaStreamWaitEvent(s2, evFork, 0);
    cudaMemsetAsync(p_cnt, 0, (size_t)n * sizeof(int), s2);
    k_cnt<<<(e / 4 + 255) / 256, 256, 0, s2>>>(dst, p_cnt, e);
    k_dinv<<<(n + 255) / 256, 256, 0, s2>>>(p_cnt, p_dinv, n);
    k_scan1<<<nb, SCAN_B, 0, s2>>>(p_cnt, p_scan, p_bsum, n);
    k_scan2<<<1, 128, 0, s2>>>(p_bsum, nb);
    k_scan3<<<(n + 255) / 256, 256, 0, s2>>>(p_cnt, p_scan, p_bsum, p_rowptr,
                                             p_cursor, n);
    k_fill<<<(e / 4 + 255) / 256, 256, 0, s2>>>(src, dst, p_dinv, p_cursor,
                                                p_csr, e);
    k_transpose_h<<<(HID * OUT_F + 255) / 256, 256, 0, s2>>>(W2, p_w2t, HID, OUT_F);
    cudaEventRecord(evJoin, s2);

    // ---- main stream: W1 transpose + GEMM1
    k_transpose_h<<<(IN_F * HID + 255) / 256, 256>>>(W1, p_w1t, IN_F, HID);

    const int grid_m = (n + 127) / 128;
    {
        constexpr int SMEM1 = 3 * (128 * 96 + HID * 48);  // 55296
        cudaFuncSetAttribute(k_gemm_f32a<HID, IN_F>,
                             cudaFuncAttributeMaxDynamicSharedMemorySize, SMEM1);
        k_gemm_f32a<HID, IN_F><<<grid_m, 256, SMEM1>>>(n, x, p_w1t, p_h1);
    }

    // ---- join: aggregation needs the CSR
    cudaStreamWaitEvent(0, evJoin, 0);

    k_agg_csr128<<<(n * 32 + 255) / 256, 256>>>(p_h1, p_rowptr, p_csr, p_dinv,
                                                b1, p_agg1, n);

    {
        constexpr int SMEM2 = 3 * (128 * 48 + OUT_F * 48);  // 27648
        cudaFuncSetAttribute(k_gemm_f16a<OUT_F, HID>,
                             cudaFuncAttributeMaxDynamicSharedMemorySize, SMEM2);
        k_gemm_f16a<OUT_F, HID><<<grid_m, 256, SMEM2>>>(n, p_agg1, p_w2t, p_h2);
    }

    k_agg_csr64<<<(n * 32 + 255) / 256, 256>>>(p_h2, p_rowptr, p_csr, p_dinv,
                                               b2, out, n);
}

// round 11
// speedup vs baseline: 1.3633x; 1.3633x over previous
#include <cuda_runtime.h>
#include <cuda_fp16.h>
#include <cuda_bf16.h>
#include <cstdint>

#define NMAX 100000
#define EMAX 1600000
#define IN_F 256
#define HID 128
#define OUT_F 64
#define SCAN_B 1024

// ---------------------------------------------------------------------------
// Scratch (bss, no runtime allocation)
// ---------------------------------------------------------------------------
__device__ int   g_cnt[NMAX];
__device__ int   g_scan[NMAX];
__device__ int   g_bsum[(NMAX + SCAN_B - 1) / SCAN_B];
__device__ int   g_rowptr[NMAX + 1];
__device__ int   g_cursor[NMAX];
__device__ __align__(16) int2  g_csr[EMAX];        // {src, coef-bits}
__device__ float g_dinv[NMAX];
__device__ __align__(128) __half g_h1[(size_t)NMAX * HID];    // fp16 h1
__device__ __align__(128) __half g_agg1[(size_t)NMAX * HID];  // fp16 relu(agg+b1)
__device__ __align__(128) __half g_h2[(size_t)NMAX * OUT_F];  // fp16 h2
__device__ __align__(128) __half g_w1t[HID * IN_F];   // fp16 W1^T
__device__ __align__(128) __half g_w2t[OUT_F * HID];  // fp16 W2^T

// ---------------------------------------------------------------------------
// PTX helpers (baseline PTX only)
// ---------------------------------------------------------------------------
__device__ __forceinline__ uint32_t smem_u32(const void* p) {
    uint32_t a;
    asm("{ .reg .u64 t; cvta.to.shared.u64 t, %1; cvt.u32.u64 %0, t; }"
        : "=r"(a) : "l"(p));
    return a;
}
__device__ __forceinline__ void cp_async16(uint32_t sa, const void* g) {
    asm volatile("cp.async.cg.shared.global [%0], [%1], 16;" ::"r"(sa), "l"(g));
}
__device__ __forceinline__ void cp_commit() {
    asm volatile("cp.async.commit_group;");
}
template <int N>
__device__ __forceinline__ void cp_wait() {
    asm volatile("cp.async.wait_group %0;" ::"n"(N));
}
__device__ __forceinline__ void ldsm_x4(uint32_t& r0, uint32_t& r1, uint32_t& r2,
                                        uint32_t& r3, uint32_t addr) {
    asm volatile("ldmatrix.sync.aligned.m8n8.x4.shared.b16 {%0,%1,%2,%3}, [%4];"
                 : "=r"(r0), "=r"(r1), "=r"(r2), "=r"(r3) : "r"(addr));
}
__device__ __forceinline__ float2 lds64(uint32_t addr) {
    float2 v;
    asm volatile("ld.shared.v2.f32 {%0,%1}, [%2];"
                 : "=f"(v.x), "=f"(v.y) : "r"(addr));
    return v;
}
__device__ __forceinline__ uint32_t pack_h2(float lo, float hi) {
    __half2 h = __floats2half2_rn(lo, hi);
    return *reinterpret_cast<uint32_t*>(&h);
}
__device__ __forceinline__ void mma_f16(float* c, const uint32_t* a,
                                        const uint32_t* b) {
    asm volatile(
        "mma.sync.aligned.m16n8k16.row.col.f32.f16.f16.f32 "
        "{%0,%1,%2,%3}, {%4,%5,%6,%7}, {%8,%9}, {%0,%1,%2,%3};"
        : "+f"(c[0]), "+f"(c[1]), "+f"(c[2]), "+f"(c[3])
        : "r"(a[0]), "r"(a[1]), "r"(a[2]), "r"(a[3]), "r"(b[0]), "r"(b[1]));
}

// ---------------------------------------------------------------------------
// GEMM1: A fp32 in smem -> fp16 frags via LDS.64+cvt. B plain fp16.
// ---------------------------------------------------------------------------
template <int NT, int KT>
__global__ void __launch_bounds__(256)
k_gemm_f32a(int M, const float* __restrict__ A, const __half* __restrict__ BT,
            __half* __restrict__ C) {
    constexpr int BK = 16;
    constexpr int T = KT / BK;
    constexpr int A_STR = 96;
    constexpr int B_STR = 48;
    constexpr int A_ST = 128 * A_STR;
    constexpr int B_ST = NT * B_STR;
    constexpr int STAGE = A_ST + B_ST;
    constexpr int NFRAG = NT / 16;

    extern __shared__ __align__(16) char smem[];
    const uint32_t sb = smem_u32(smem);
    const int tid = threadIdx.x;
    const int wid = tid >> 5, lane = tid & 31;
    const int warpM = wid >> 1, warpN = wid & 1;
    const int brow = blockIdx.x * 128;

    float acc[2][NFRAG][4];
#pragma unroll
    for (int i = 0; i < 2; i++)
#pragma unroll
        for (int j = 0; j < NFRAG; j++)
#pragma unroll
            for (int q = 0; q < 4; q++) acc[i][j][q] = 0.f;

    auto prefetch = [&](int t, int s) {
        const uint32_t ao = sb + s * STAGE;
        const uint32_t bo = ao + A_ST;
#pragma unroll
        for (int i = tid; i < 128 * 4; i += 256) {
            int m = i >> 2, q = i & 3;
            int gr = brow + m;
            if (gr >= M) gr = M - 1;
            cp_async16(ao + m * A_STR + q * 16,
                       A + (size_t)gr * KT + t * BK + q * 4);
        }
#pragma unroll
        for (int i = tid; i < NT * 2; i += 256) {
            int r = i >> 1, q = i & 1;
            cp_async16(bo + r * B_STR + q * 16,
                       BT + (size_t)r * KT + t * BK + q * 8);
        }
        cp_commit();
    };

    prefetch(0, 0);
    if (T > 1) prefetch(1, 1);

    const int ti = lane >> 3, ri = lane & 7;
    const int r4 = lane >> 2, c4 = lane & 3;

    for (int t = 0; t < T; t++) {
        const int s = t % 3;
        if (t + 1 < T) cp_wait<1>(); else cp_wait<0>();
        __syncthreads();
        if (t + 2 < T) prefetch(t + 2, (t + 2) % 3);

        const uint32_t ao = sb + s * STAGE;
        const uint32_t bo = ao + A_ST;

        uint32_t af[2][4];
#pragma unroll
        for (int mf = 0; mf < 2; mf++) {
            int m0 = warpM * 32 + mf * 16 + r4;
            uint32_t b0 = ao + m0 * A_STR + c4 * 8;
            uint32_t b1 = ao + (m0 + 8) * A_STR + c4 * 8;
            float2 f00 = lds64(b0);
            float2 f10 = lds64(b1);
            float2 f01 = lds64(b0 + 32);
            float2 f11 = lds64(b1 + 32);
            af[mf][0] = pack_h2(f00.x, f00.y);
            af[mf][1] = pack_h2(f10.x, f10.y);
            af[mf][2] = pack_h2(f01.x, f01.y);
            af[mf][3] = pack_h2(f11.x, f11.y);
        }
        uint32_t bf[NFRAG][2];
#pragma unroll
        for (int fp = 0; fp < NFRAG / 2; fp++) {
            int nr = warpN * (NT / 2) + fp * 16 + (ti >> 1) * 8 + ri;
            uint32_t off = nr * B_STR + (ti & 1) * 16;
            ldsm_x4(bf[2 * fp][0], bf[2 * fp][1], bf[2 * fp + 1][0],
                    bf[2 * fp + 1][1], bo + off);
        }
#pragma unroll
        for (int mf = 0; mf < 2; mf++)
#pragma unroll
            for (int nf = 0; nf < NFRAG; nf++)
                mma_f16(acc[mf][nf], af[mf], bf[nf]);
    }

#pragma unroll
    for (int mf = 0; mf < 2; mf++) {
        int row0 = brow + warpM * 32 + mf * 16 + (lane >> 2);
        int row1 = row0 + 8;
#pragma unroll
        for (int nf = 0; nf < NFRAG; nf++) {
            int col = warpN * (NT / 2) + nf * 8 + (lane & 3) * 2;
            if (row0 < M)
                *reinterpret_cast<__half2*>(C + (size_t)row0 * NT + col) =
                    __floats2half2_rn(acc[mf][nf][0], acc[mf][nf][1]);
            if (row1 < M)
                *reinterpret_cast<__half2*>(C + (size_t)row1 * NT + col) =
                    __floats2half2_rn(acc[mf][nf][2], acc[mf][nf][3]);
        }
    }
}

// ---------------------------------------------------------------------------
// GEMM2: A fp16 (agg1), B plain fp16.
// ---------------------------------------------------------------------------
template <int NT, int KT>
__global__ void __launch_bounds__(256)
k_gemm_f16a(int M, const __half* __restrict__ A, const __half* __restrict__ BT,
            __half* __restrict__ C) {
    constexpr int BK = 16;
    constexpr int T = KT / BK;
    constexpr int STR = 48;
    constexpr int A_ST = 128 * STR;
    constexpr int B_ST = NT * STR;
    constexpr int STAGE = A_ST + B_ST;
    constexpr int NFRAG = NT / 16;

    extern __shared__ __align__(16) char smem[];
    const uint32_t sb = smem_u32(smem);
    const int tid = threadIdx.x;
    const int wid = tid >> 5, lane = tid & 31;
    const int warpM = wid >> 1, warpN = wid & 1;
    const int brow = blockIdx.x * 128;

    float acc[2][NFRAG][4];
#pragma unroll
    for (int i = 0; i < 2; i++)
#pragma unroll
        for (int j = 0; j < NFRAG; j++)
#pragma unroll
            for (int q = 0; q < 4; q++) acc[i][j][q] = 0.f;

    auto prefetch = [&](int t, int s) {
        const uint32_t ao = sb + s * STAGE;
        const uint32_t bo = ao + A_ST;
#pragma unroll
        for (int i = tid; i < 128 * 2; i += 256) {
            int m = i >> 1, q = i & 1;
            int gr = brow + m;
            if (gr >= M) gr = M - 1;
            cp_async16(ao + m * STR + q * 16,
                       A + (size_t)gr * KT + t * BK + q * 8);
        }
#pragma unroll
        for (int i = tid; i < NT * 2; i += 256) {
            int r = i >> 1, q = i & 1;
            cp_async16(bo + r * STR + q * 16,
                       BT + (size_t)r * KT + t * BK + q * 8);
        }
        cp_commit();
    };

    prefetch(0, 0);
    if (T > 1) prefetch(1, 1);

    const int ti = lane >> 3, ri = lane & 7;

    for (int t = 0; t < T; t++) {
        const int s = t % 3;
        if (t + 1 < T) cp_wait<1>(); else cp_wait<0>();
        __syncthreads();
        if (t + 2 < T) prefetch(t + 2, (t + 2) % 3);

        const uint32_t ao = sb + s * STAGE;
        const uint32_t bo = ao + A_ST;

        uint32_t af[2][4];
#pragma unroll
        for (int mf = 0; mf < 2; mf++) {
            int m = warpM * 32 + mf * 16 + (ti & 1) * 8 + ri;
            uint32_t addr = ao + m * STR + (ti >> 1) * 16;
            ldsm_x4(af[mf][0], af[mf][1], af[mf][2], af[mf][3], addr);
        }
        uint32_t bf[NFRAG][2];
#pragma unroll
        for (int fp = 0; fp < NFRAG / 2; fp++) {
            int nr = warpN * (NT / 2) + fp * 16 + (ti >> 1) * 8 + ri;
            uint32_t off = nr * STR + (ti & 1) * 16;
            ldsm_x4(bf[2 * fp][0], bf[2 * fp][1], bf[2 * fp + 1][0],
                    bf[2 * fp + 1][1], bo + off);
        }
#pragma unroll
        for (int mf = 0; mf < 2; mf++)
#pragma unroll
            for (int nf = 0; nf < NFRAG; nf++)
                mma_f16(acc[mf][nf], af[mf], bf[nf]);
    }

#pragma unroll
    for (int mf = 0; mf < 2; mf++) {
        int row0 = brow + warpM * 32 + mf * 16 + (lane >> 2);
        int row1 = row0 + 8;
#pragma unroll
        for (int nf = 0; nf < NFRAG; nf++) {
            int col = warpN * (NT / 2) + nf * 8 + (lane & 3) * 2;
            if (row0 < M)
                *reinterpret_cast<__half2*>(C + (size_t)row0 * NT + col) =
                    __floats2half2_rn(acc[mf][nf][0], acc[mf][nf][1]);
            if (row1 < M)
                *reinterpret_cast<__half2*>(C + (size_t)row1 * NT + col) =
                    __floats2half2_rn(acc[mf][nf][2], acc[mf][nf][3]);
        }
    }
}

// ---------------------------------------------------------------------------
// Weight transpose -> fp16
// ---------------------------------------------------------------------------
__global__ void k_transpose_h(const float* __restrict__ W,
                              __half* __restrict__ WT, int K, int N) {
    int i = blockIdx.x * blockDim.x + threadIdx.x;
    if (i >= K * N) return;
    int k = i / N, nn = i % N;
    WT[(size_t)nn * K + k] = __float2half_rn(W[i]);
}

// ---------------------------------------------------------------------------
// CSR build (side stream)
// ---------------------------------------------------------------------------
__global__ void k_cnt(const int* __restrict__ dst, int* cnt, int e) {
    int i = blockIdx.x * blockDim.x + threadIdx.x;
    int base = i * 4;
    if (base + 3 < e) {
        int4 d = *reinterpret_cast<const int4*>(dst + base);
        atomicAdd(&cnt[d.x], 1);
        atomicAdd(&cnt[d.y], 1);
        atomicAdd(&cnt[d.z], 1);
        atomicAdd(&cnt[d.w], 1);
    } else {
        for (int j = base; j < e; j++) atomicAdd(&cnt[dst[j]], 1);
    }
}
__global__ void k_dinv(const int* __restrict__ cnt, float* dinv, int n) {
    int i = blockIdx.x * blockDim.x + threadIdx.x;
    if (i < n) dinv[i] = rsqrtf((float)(cnt[i] + 1));
}
__global__ void k_scan1(const int* __restrict__ cnt, int* scan, int* bsum, int n) {
    __shared__ int sh[SCAN_B];
    int i = blockIdx.x * SCAN_B + threadIdx.x;
    int v = (i < n) ? cnt[i] : 0;
    sh[threadIdx.x] = v;
    __syncthreads();
#pragma unroll
    for (int off = 1; off < SCAN_B; off <<= 1) {
        int t = (threadIdx.x >= off) ? sh[threadIdx.x - off] : 0;
        __syncthreads();
        sh[threadIdx.x] += t;
        __syncthreads();
    }
    if (i < n) scan[i] = sh[threadIdx.x];
    if (threadIdx.x == SCAN_B - 1) bsum[blockIdx.x] = sh[SCAN_B - 1];
}
__global__ void k_scan2(int* bsum, int nb) {
    __shared__ int sh[128];
    int v = (threadIdx.x < nb) ? bsum[threadIdx.x] : 0;
    sh[threadIdx.x] = v;
    __syncthreads();
#pragma unroll
    for (int off = 1; off < 128; off <<= 1) {
        int t = (threadIdx.x >= off) ? sh[threadIdx.x - off] : 0;
        __syncthreads();
        sh[threadIdx.x] += t;
        __syncthreads();
    }
    if (threadIdx.x < nb) bsum[threadIdx.x] = sh[threadIdx.x] - v;
}
__global__ void k_scan3(const int* __restrict__ cnt, const int* __restrict__ scan,
                        const int* __restrict__ bsum, int* rowptr, int* cursor, int n) {
    int i = blockIdx.x * blockDim.x + threadIdx.x;
    if (i >= n) return;
    int excl = scan[i] - cnt[i] + bsum[i / SCAN_B];
    rowptr[i] = excl;
    cursor[i] = excl;
    if (i == n - 1) rowptr[n] = excl + cnt[i];
}
__global__ void k_fill(const int* __restrict__ src, const int* __restrict__ dst,
                       const float* __restrict__ dinv, int* cursor,
                       int2* __restrict__ csr, int e) {
    int i = blockIdx.x * blockDim.x + threadIdx.x;
    int base = i * 4;
    if (base + 3 < e) {
        int4 sv = *reinterpret_cast<const int4*>(src + base);
        int4 dv = *reinterpret_cast<const int4*>(dst + base);
        const int ss[4] = {sv.x, sv.y, sv.z, sv.w};
        const int dd[4] = {dv.x, dv.y, dv.z, dv.w};
#pragma unroll
        for (int j = 0; j < 4; j++) {
            int pos = atomicAdd(&cursor[dd[j]], 1);
            csr[pos] = make_int2(ss[j],
                                 __float_as_int(dinv[ss[j]] * dinv[dd[j]]));
        }
    } else {
        for (int j = base; j < e; j++) {
            int s = src[j], d = dst[j];
            int pos = atomicAdd(&cursor[d], 1);
            csr[pos] = make_int2(s, __float_as_int(dinv[s] * dinv[d]));
        }
    }
}

// ---------------------------------------------------------------------------
// Warp-per-node aggregation (fp16 gathers) — R9 2-edge loop form.
// agg1: +b1, relu, fp16 out.
// ---------------------------------------------------------------------------
__global__ void k_agg_csr128(const __half* __restrict__ h,
                             const int* __restrict__ rowptr,
                             const int2* __restrict__ csr,
                             const float* __restrict__ dinv,
                             const float* __restrict__ b1,
                             __half* __restrict__ out, int n) {
    int node = (blockIdx.x * blockDim.x + threadIdx.x) >> 5;
    int lane = threadIdx.x & 31;
    if (node >= n) return;
    float di = dinv[node];
    float c = di * di;
    uint2 raw = *reinterpret_cast<const uint2*>(h + (size_t)node * 128 + lane * 4);
    float2 p0 = __half22float2(*reinterpret_cast<const __half2*>(&raw.x));
    float2 p1 = __half22float2(*reinterpret_cast<const __half2*>(&raw.y));
    float4 acc = make_float4(p0.x * c, p0.y * c, p1.x * c, p1.y * c);
    int idx = rowptr[node], end = rowptr[node + 1];
    for (; idx + 1 < end; idx += 2) {
        int2 e0 = csr[idx];
        int2 e1 = csr[idx + 1];
        float c0 = __int_as_float(e0.y);
        float c1 = __int_as_float(e1.y);
        uint2 r0 = *reinterpret_cast<const uint2*>(h + (size_t)e0.x * 128 + lane * 4);
        uint2 r1 = *reinterpret_cast<const uint2*>(h + (size_t)e1.x * 128 + lane * 4);
        float2 a0 = __half22float2(*reinterpret_cast<const __half2*>(&r0.x));
        float2 a1 = __half22float2(*reinterpret_cast<const __half2*>(&r0.y));
        float2 b0 = __half22float2(*reinterpret_cast<const __half2*>(&r1.x));
        float2 b1v = __half22float2(*reinterpret_cast<const __half2*>(&r1.y));
        acc.x = fmaf(a0.x, c0, acc.x); acc.y = fmaf(a0.y, c0, acc.y);
        acc.z = fmaf(a1.x, c0, acc.z); acc.w = fmaf(a1.y, c0, acc.w);
        acc.x = fmaf(b0.x, c1, acc.x); acc.y = fmaf(b0.y, c1, acc.y);
        acc.z = fmaf(b1v.x, c1, acc.z); acc.w = fmaf(b1v.y, c1, acc.w);
    }
    if (idx < end) {
        int2 e0 = csr[idx];
        float c0 = __int_as_float(e0.y);
        uint2 r0 = *reinterpret_cast<const uint2*>(h + (size_t)e0.x * 128 + lane * 4);
        float2 a0 = __half22float2(*reinterpret_cast<const __half2*>(&r0.x));
        float2 a1 = __half22float2(*reinterpret_cast<const __half2*>(&r0.y));
        acc.x = fmaf(a0.x, c0, acc.x); acc.y = fmaf(a0.y, c0, acc.y);
        acc.z = fmaf(a1.x, c0, acc.z); acc.w = fmaf(a1.y, c0, acc.w);
    }
    float4 b = *reinterpret_cast<const float4*>(b1 + lane * 4);
    __half2 o0 = __floats2half2_rn(fmaxf(acc.x + b.x, 0.f), fmaxf(acc.y + b.y, 0.f));
    __half2 o1 = __floats2half2_rn(fmaxf(acc.z + b.z, 0.f), fmaxf(acc.w + b.w, 0.f));
    uint2 o;
    o.x = *reinterpret_cast<uint32_t*>(&o0);
    o.y = *reinterpret_cast<uint32_t*>(&o1);
    *reinterpret_cast<uint2*>(out + (size_t)node * 128 + lane * 4) = o;
}

__global__ void k_agg_csr64(const __half* __restrict__ h,
                            const int* __restrict__ rowptr,
                            const int2* __restrict__ csr,
                            const float* __restrict__ dinv,
                            const float* __restrict__ bias,
                            float* __restrict__ out, int n) {
    int node = (blockIdx.x * blockDim.x + threadIdx.x) >> 5;
    int lane = threadIdx.x & 31;
    if (node >= n) return;
    float di = dinv[node];
    float c = di * di;
    uint32_t raw = *reinterpret_cast<const uint32_t*>(h + (size_t)node * 64 + lane * 2);
    float2 v = __half22float2(*reinterpret_cast<const __half2*>(&raw));
    float2 acc = make_float2(v.x * c, v.y * c);
    int idx = rowptr[node], end = rowptr[node + 1];
    for (; idx + 1 < end; idx += 2) {
        int2 e0 = csr[idx];
        int2 e1 = csr[idx + 1];
        float c0 = __int_as_float(e0.y);
        float c1 = __int_as_float(e1.y);
        uint32_t r0 = *reinterpret_cast<const uint32_t*>(h + (size_t)e0.x * 64 + lane * 2);
        uint32_t r1 = *reinterpret_cast<const uint32_t*>(h + (size_t)e1.x * 64 + lane * 2);
        float2 v0 = __half22float2(*reinterpret_cast<const __half2*>(&r0));
        float2 v1 = __half22float2(*reinterpret_cast<const __half2*>(&r1));
        acc.x = fmaf(v0.x, c0, acc.x); acc.y = fmaf(v0.y, c0, acc.y);
        acc.x = fmaf(v1.x, c1, acc.x); acc.y = fmaf(v1.y, c1, acc.y);
    }
    if (idx < end) {
        int2 e0 = csr[idx];
        float c0 = __int_as_float(e0.y);
        uint32_t r0 = *reinterpret_cast<const uint32_t*>(h + (size_t)e0.x * 64 + lane * 2);
        float2 v0 = __half22float2(*reinterpret_cast<const __half2*>(&r0));
        acc.x = fmaf(v0.x, c0, acc.x); acc.y = fmaf(v0.y, c0, acc.y);
    }
    float2 b = *reinterpret_cast<const float2*>(bias + lane * 2);
    acc.x += b.x;
    acc.y += b.y;
    *reinterpret_cast<float2*>(out + (size_t)node * 64 + lane * 2) = acc;
}

// ---------------------------------------------------------------------------
// Launch
// ---------------------------------------------------------------------------
extern "C" void kernel_launch(void* const* d_in, const int* in_sizes, int n_in,
                              void* d_out, int out_size) {
    const float* x = (const float*)d_in[0];
    const int* ei = (const int*)d_in[1];
    const float* W1 = (const float*)d_in[2];
    const float* b1 = (const float*)d_in[3];
    const float* W2 = (const float*)d_in[4];
    const float* b2 = (const float*)d_in[5];
    float* out = (float*)d_out;

    const int n = in_sizes[0] / IN_F;  // 100000
    const int e = in_sizes[1] / 2;     // 1600000
    const int* src = ei;
    const int* dst = ei + e;
    const int nb = (n + SCAN_B - 1) / SCAN_B;

    int *p_cnt, *p_scan, *p_bsum, *p_rowptr, *p_cursor;
    int2* p_csr;
    float* p_dinv;
    __half *p_h1, *p_agg1, *p_h2, *p_w1t, *p_w2t;
    cudaGetSymbolAddress((void**)&p_cnt, g_cnt);
    cudaGetSymbolAddress((void**)&p_scan, g_scan);
    cudaGetSymbolAddress((void**)&p_bsum, g_bsum);
    cudaGetSymbolAddress((void**)&p_rowptr, g_rowptr);
    cudaGetSymbolAddress((void**)&p_cursor, g_cursor);
    cudaGetSymbolAddress((void**)&p_csr, g_csr);
    cudaGetSymbolAddress((void**)&p_dinv, g_dinv);
    cudaGetSymbolAddress((void**)&p_h1, g_h1);
    cudaGetSymbolAddress((void**)&p_agg1, g_agg1);
    cudaGetSymbolAddress((void**)&p_h2, g_h2);
    cudaGetSymbolAddress((void**)&p_w1t, g_w1t);
    cudaGetSymbolAddress((void**)&p_w2t, g_w2t);

    static cudaStream_t s2 = nullptr;
    static cudaEvent_t evFork = nullptr, evJoin = nullptr;
    if (s2 == nullptr) {
        cudaStreamCreateWithFlags(&s2, cudaStreamNonBlocking);
        cudaEventCreateWithFlags(&evFork, cudaEventDisableTiming);
        cudaEventCreateWithFlags(&evJoin, cudaEventDisableTiming);
    }

    // ---- fork: CSR build + W2 transpose on side stream
    cudaEventRecord(evFork, 0);
    cudaStreamWaitEvent(s2, evFork, 0);
    cudaMemsetAsync(p_cnt, 0, (size_t)n * sizeof(int), s2);
    k_cnt<<<(e / 4 + 255) / 256, 256, 0, s2>>>(dst, p_cnt, e);
    k_dinv<<<(n + 255) / 256, 256, 0, s2>>>(p_cnt, p_dinv, n);
    k_scan1<<<nb, SCAN_B, 0, s2>>>(p_cnt, p_scan, p_bsum, n);
    k_scan2<<<1, 128, 0, s2>>>(p_bsum, nb);
    k_scan3<<<(n + 255) / 256, 256, 0, s2>>>(p_cnt, p_scan, p_bsum, p_rowptr,
                                             p_cursor, n);
    k_fill<<<(e / 4 + 255) / 256, 256, 0, s2>>>(src, dst, p_dinv, p_cursor,
                                                p_csr, e);
    k_transpose_h<<<(HID * OUT_F + 255) / 256, 256, 0, s2>>>(W2, p_w2t, HID, OUT_F);
    cudaEventRecord(evJoin, s2);

    // ---- main stream: W1 transpose + GEMM1
    k_transpose_h<<<(IN_F * HID + 255) / 256, 256>>>(W1, p_w1t, IN_F, HID);

    const int grid_m = (n + 127) / 128;
    {
        constexpr int SMEM1 = 3 * (128 * 96 + HID * 48);  // 55296
        cudaFuncSetAttribute(k_gemm_f32a<HID, IN_F>,
                             cudaFuncAttributeMaxDynamicSharedMemorySize, SMEM1);
        k_gemm_f32a<HID, IN_F><<<grid_m, 256, SMEM1>>>(n, x, p_w1t, p_h1);
    }

    // ---- join: aggregation needs the CSR
    cudaStreamWaitEvent(0, evJoin, 0);

    k_agg_csr128<<<(n * 32 + 255) / 256, 256>>>(p_h1, p_rowptr, p_csr, p_dinv,
                                                b1, p_agg1, n);

    {
        constexpr int SMEM2 = 3 * (128 * 48 + OUT_F * 48);  // 27648
        cudaFuncSetAttribute(k_gemm_f16a<OUT_F, HID>,
                             cudaFuncAttributeMaxDynamicSharedMemorySize, SMEM2);
        k_gemm_f16a<OUT_F, HID><<<grid_m, 256, SMEM2>>>(n, p_agg1, p_w2t, p_h2);
    }

    k_agg_csr64<<<(n * 32 + 255) / 256, 256>>>(p_h2, p_rowptr, p_csr, p_dinv,
                                               b2, out, n);
}

// round 13
// speedup vs baseline: 1.3723x; 1.0066x over previous
#include <cuda_runtime.h>
#include <cuda_fp16.h>
#include <cuda_bf16.h>
#include <cstdint>

#define NMAX 100000
#define EMAX 1600000
#define IN_F 256
#define HID 128
#define OUT_F 64
#define SCAN_B 1024

// ---------------------------------------------------------------------------
// Scratch (bss, no runtime allocation). g_cnt: zero-init at load, re-zeroed by
// k_zero at the end of every call (so each graph replay sees zeros).
// ---------------------------------------------------------------------------
__device__ int   g_cnt[NMAX];
__device__ int   g_scan[NMAX];
__device__ int   g_bsum[(NMAX + SCAN_B - 1) / SCAN_B];
__device__ int   g_rowptr[NMAX + 1];
__device__ int   g_cursor[NMAX];
__device__ __align__(16) int2  g_csr[EMAX];        // {src, coef-bits}
__device__ float g_dinv[NMAX];
__device__ __align__(128) __half g_h1[(size_t)NMAX * HID];
__device__ __align__(128) __half g_agg1[(size_t)NMAX * HID];
__device__ __align__(128) __half g_h2[(size_t)NMAX * OUT_F];
__device__ __align__(128) __half g_w1t[HID * IN_F];
__device__ __align__(128) __half g_w2t[OUT_F * HID];

// ---------------------------------------------------------------------------
// PTX helpers (baseline PTX only)
// ---------------------------------------------------------------------------
__device__ __forceinline__ uint32_t smem_u32(const void* p) {
    uint32_t a;
    asm("{ .reg .u64 t; cvta.to.shared.u64 t, %1; cvt.u32.u64 %0, t; }"
        : "=r"(a) : "l"(p));
    return a;
}
__device__ __forceinline__ void cp_async16(uint32_t sa, const void* g) {
    asm volatile("cp.async.cg.shared.global [%0], [%1], 16;" ::"r"(sa), "l"(g));
}
__device__ __forceinline__ void cp_commit() {
    asm volatile("cp.async.commit_group;");
}
template <int N>
__device__ __forceinline__ void cp_wait() {
    asm volatile("cp.async.wait_group %0;" ::"n"(N));
}
__device__ __forceinline__ void ldsm_x4(uint32_t& r0, uint32_t& r1, uint32_t& r2,
                                        uint32_t& r3, uint32_t addr) {
    asm volatile("ldmatrix.sync.aligned.m8n8.x4.shared.b16 {%0,%1,%2,%3}, [%4];"
                 : "=r"(r0), "=r"(r1), "=r"(r2), "=r"(r3) : "r"(addr));
}
__device__ __forceinline__ float2 lds64(uint32_t addr) {
    float2 v;
    asm volatile("ld.shared.v2.f32 {%0,%1}, [%2];"
                 : "=f"(v.x), "=f"(v.y) : "r"(addr));
    return v;
}
__device__ __forceinline__ uint32_t pack_h2(float lo, float hi) {
    __half2 h = __floats2half2_rn(lo, hi);
    return *reinterpret_cast<uint32_t*>(&h);
}
__device__ __forceinline__ void mma_f16(float* c, const uint32_t* a,
                                        const uint32_t* b) {
    asm volatile(
        "mma.sync.aligned.m16n8k16.row.col.f32.f16.f16.f32 "
        "{%0,%1,%2,%3}, {%4,%5,%6,%7}, {%8,%9}, {%0,%1,%2,%3};"
        : "+f"(c[0]), "+f"(c[1]), "+f"(c[2]), "+f"(c[3])
        : "r"(a[0]), "r"(a[1]), "r"(a[2]), "r"(a[3]), "r"(b[0]), "r"(b[1]));
}

// ---------------------------------------------------------------------------
// GEMM1: A fp32 in smem -> fp16 frags via LDS.64+cvt. B plain fp16.
// ---------------------------------------------------------------------------
template <int NT, int KT>
__global__ void __launch_bounds__(256)
k_gemm_f32a(int M, const float* __restrict__ A, const __half* __restrict__ BT,
            __half* __restrict__ C) {
    constexpr int BK = 16;
    constexpr int T = KT / BK;
    constexpr int A_STR = 96;
    constexpr int B_STR = 48;
    constexpr int A_ST = 128 * A_STR;
    constexpr int B_ST = NT * B_STR;
    constexpr int STAGE = A_ST + B_ST;
    constexpr int NFRAG = NT / 16;

    extern __shared__ __align__(16) char smem[];
    const uint32_t sb = smem_u32(smem);
    const int tid = threadIdx.x;
    const int wid = tid >> 5, lane = tid & 31;
    const int warpM = wid >> 1, warpN = wid & 1;
    const int brow = blockIdx.x * 128;

    float acc[2][NFRAG][4];
#pragma unroll
    for (int i = 0; i < 2; i++)
#pragma unroll
        for (int j = 0; j < NFRAG; j++)
#pragma unroll
            for (int q = 0; q < 4; q++) acc[i][j][q] = 0.f;

    auto prefetch = [&](int t, int s) {
        const uint32_t ao = sb + s * STAGE;
        const uint32_t bo = ao + A_ST;
#pragma unroll
        for (int i = tid; i < 128 * 4; i += 256) {
            int m = i >> 2, q = i & 3;
            int gr = brow + m;
            if (gr >= M) gr = M - 1;
            cp_async16(ao + m * A_STR + q * 16,
                       A + (size_t)gr * KT + t * BK + q * 4);
        }
#pragma unroll
        for (int i = tid; i < NT * 2; i += 256) {
            int r = i >> 1, q = i & 1;
            cp_async16(bo + r * B_STR + q * 16,
                       BT + (size_t)r * KT + t * BK + q * 8);
        }
        cp_commit();
    };

    prefetch(0, 0);
    if (T > 1) prefetch(1, 1);

    const int ti = lane >> 3, ri = lane & 7;
    const int r4 = lane >> 2, c4 = lane & 3;

    for (int t = 0; t < T; t++) {
        const int s = t % 3;
        if (t + 1 < T) cp_wait<1>(); else cp_wait<0>();
        __syncthreads();
        if (t + 2 < T) prefetch(t + 2, (t + 2) % 3);

        const uint32_t ao = sb + s * STAGE;
        const uint32_t bo = ao + A_ST;

        uint32_t af[2][4];
#pragma unroll
        for (int mf = 0; mf < 2; mf++) {
            int m0 = warpM * 32 + mf * 16 + r4;
            uint32_t b0 = ao + m0 * A_STR + c4 * 8;
            uint32_t b1 = ao + (m0 + 8) * A_STR + c4 * 8;
            float2 f00 = lds64(b0);
            float2 f10 = lds64(b1);
            float2 f01 = lds64(b0 + 32);
            float2 f11 = lds64(b1 + 32);
            af[mf][0] = pack_h2(f00.x, f00.y);
            af[mf][1] = pack_h2(f10.x, f10.y);
            af[mf][2] = pack_h2(f01.x, f01.y);
            af[mf][3] = pack_h2(f11.x, f11.y);
        }
        uint32_t bf[NFRAG][2];
#pragma unroll
        for (int fp = 0; fp < NFRAG / 2; fp++) {
            int nr = warpN * (NT / 2) + fp * 16 + (ti >> 1) * 8 + ri;
            uint32_t off = nr * B_STR + (ti & 1) * 16;
            ldsm_x4(bf[2 * fp][0], bf[2 * fp][1], bf[2 * fp + 1][0],
                    bf[2 * fp + 1][1], bo + off);
        }
#pragma unroll
        for (int mf = 0; mf < 2; mf++)
#pragma unroll
            for (int nf = 0; nf < NFRAG; nf++)
                mma_f16(acc[mf][nf], af[mf], bf[nf]);
    }

#pragma unroll
    for (int mf = 0; mf < 2; mf++) {
        int row0 = brow + warpM * 32 + mf * 16 + (lane >> 2);
        int row1 = row0 + 8;
#pragma unroll
        for (int nf = 0; nf < NFRAG; nf++) {
            int col = warpN * (NT / 2) + nf * 8 + (lane & 3) * 2;
            if (row0 < M)
                *reinterpret_cast<__half2*>(C + (size_t)row0 * NT + col) =
                    __floats2half2_rn(acc[mf][nf][0], acc[mf][nf][1]);
            if (row1 < M)
                *reinterpret_cast<__half2*>(C + (size_t)row1 * NT + col) =
                    __floats2half2_rn(acc[mf][nf][2], acc[mf][nf][3]);
        }
    }
}

// ---------------------------------------------------------------------------
// GEMM2: A fp16 (agg1), B plain fp16.
// ---------------------------------------------------------------------------
template <int NT, int KT>
__global__ void __launch_bounds__(256)
k_gemm_f16a(int M, const __half* __restrict__ A, const __half* __restrict__ BT,
            __half* __restrict__ C) {
    constexpr int BK = 16;
    constexpr int T = KT / BK;
    constexpr int STR = 48;
    constexpr int A_ST = 128 * STR;
    constexpr int B_ST = NT * STR;
    constexpr int STAGE = A_ST + B_ST;
    constexpr int NFRAG = NT / 16;

    extern __shared__ __align__(16) char smem[];
    const uint32_t sb = smem_u32(smem);
    const int tid = threadIdx.x;
    const int wid = tid >> 5, lane = tid & 31;
    const int warpM = wid >> 1, warpN = wid & 1;
    const int brow = blockIdx.x * 128;

    float acc[2][NFRAG][4];
#pragma unroll
    for (int i = 0; i < 2; i++)
#pragma unroll
        for (int j = 0; j < NFRAG; j++)
#pragma unroll
            for (int q = 0; q < 4; q++) acc[i][j][q] = 0.f;

    auto prefetch = [&](int t, int s) {
        const uint32_t ao = sb + s * STAGE;
        const uint32_t bo = ao + A_ST;
#pragma unroll
        for (int i = tid; i < 128 * 2; i += 256) {
            int m = i >> 1, q = i & 1;
            int gr = brow + m;
            if (gr >= M) gr = M - 1;
            cp_async16(ao + m * STR + q * 16,
                       A + (size_t)gr * KT + t * BK + q * 8);
        }
#pragma unroll
        for (int i = tid; i < NT * 2; i += 256) {
            int r = i >> 1, q = i & 1;
            cp_async16(bo + r * STR + q * 16,
                       BT + (size_t)r * KT + t * BK + q * 8);
        }
        cp_commit();
    };

    prefetch(0, 0);
    if (T > 1) prefetch(1, 1);

    const int ti = lane >> 3, ri = lane & 7;

    for (int t = 0; t < T; t++) {
        const int s = t % 3;
        if (t + 1 < T) cp_wait<1>(); else cp_wait<0>();
        __syncthreads();
        if (t + 2 < T) prefetch(t + 2, (t + 2) % 3);

        const uint32_t ao = sb + s * STAGE;
        const uint32_t bo = ao + A_ST;

        uint32_t af[2][4];
#pragma unroll
        for (int mf = 0; mf < 2; mf++) {
            int m = warpM * 32 + mf * 16 + (ti & 1) * 8 + ri;
            uint32_t addr = ao + m * STR + (ti >> 1) * 16;
            ldsm_x4(af[mf][0], af[mf][1], af[mf][2], af[mf][3], addr);
        }
        uint32_t bf[NFRAG][2];
#pragma unroll
        for (int fp = 0; fp < NFRAG / 2; fp++) {
            int nr = warpN * (NT / 2) + fp * 16 + (ti >> 1) * 8 + ri;
            uint32_t off = nr * STR + (ti & 1) * 16;
            ldsm_x4(bf[2 * fp][0], bf[2 * fp][1], bf[2 * fp + 1][0],
                    bf[2 * fp + 1][1], bo + off);
        }
#pragma unroll
        for (int mf = 0; mf < 2; mf++)
#pragma unroll
            for (int nf = 0; nf < NFRAG; nf++)
                mma_f16(acc[mf][nf], af[mf], bf[nf]);
    }

#pragma unroll
    for (int mf = 0; mf < 2; mf++) {
        int row0 = brow + warpM * 32 + mf * 16 + (lane >> 2);
        int row1 = row0 + 8;
#pragma unroll
        for (int nf = 0; nf < NFRAG; nf++) {
            int col = warpN * (NT / 2) + nf * 8 + (lane & 3) * 2;
            if (row0 < M)
                *reinterpret_cast<__half2*>(C + (size_t)row0 * NT + col) =
                    __floats2half2_rn(acc[mf][nf][0], acc[mf][nf][1]);
            if (row1 < M)
                *reinterpret_cast<__half2*>(C + (size_t)row1 * NT + col) =
                    __floats2half2_rn(acc[mf][nf][2], acc[mf][nf][3]);
        }
    }
}

// ---------------------------------------------------------------------------
// Weight transpose -> fp16
// ---------------------------------------------------------------------------
__global__ void k_transpose_h(const float* __restrict__ W,
                              __half* __restrict__ WT, int K, int N) {
    int i = blockIdx.x * blockDim.x + threadIdx.x;
    if (i >= K * N) return;
    int k = i / N, nn = i % N;
    WT[(size_t)nn * K + k] = __float2half_rn(W[i]);
}

// ---------------------------------------------------------------------------
// CSR build (side stream): cnt -> scan1 -> scan3(fused bsum-scan+dinv) -> fill
// ---------------------------------------------------------------------------
__global__ void k_cnt(const int* __restrict__ dst, int* cnt, int e) {
    int i = blockIdx.x * blockDim.x + threadIdx.x;
    int base = i * 4;
    if (base + 3 < e) {
        int4 d = *reinterpret_cast<const int4*>(dst + base);
        atomicAdd(&cnt[d.x], 1);
        atomicAdd(&cnt[d.y], 1);
        atomicAdd(&cnt[d.z], 1);
        atomicAdd(&cnt[d.w], 1);
    } else {
        for (int j = base; j < e; j++) atomicAdd(&cnt[dst[j]], 1);
    }
}
__global__ void k_scan1(const int* __restrict__ cnt, int* scan, int* bsum, int n) {
    __shared__ int sh[SCAN_B];
    int i = blockIdx.x * SCAN_B + threadIdx.x;
    int v = (i < n) ? cnt[i] : 0;
    sh[threadIdx.x] = v;
    __syncthreads();
#pragma unroll
    for (int off = 1; off < SCAN_B; off <<= 1) {
        int t = (threadIdx.x >= off) ? sh[threadIdx.x - off] : 0;
        __syncthreads();
        sh[threadIdx.x] += t;
        __syncthreads();
    }
    if (i < n) scan[i] = sh[threadIdx.x];
    if (threadIdx.x == SCAN_B - 1) bsum[blockIdx.x] = sh[SCAN_B - 1];
}
// Fused: per-block redundant scan of bsum (<=128 entries) + rowptr/cursor/dinv
__global__ void k_scan3(const int* __restrict__ cnt, const int* __restrict__ scan,
                        const int* __restrict__ bsum, int* rowptr, int* cursor,
                        float* dinv, int n, int nb) {
    __shared__ int sb[128];
    int t = threadIdx.x;
    if (t < 128) sb[t] = (t < nb) ? bsum[t] : 0;
    __syncthreads();
#pragma unroll
    for (int off = 1; off < 128; off <<= 1) {
        int tmp = (t < 128 && t >= off) ? sb[t - off] : 0;
        __syncthreads();
        if (t < 128) sb[t] += tmp;
        __syncthreads();
    }
    int i = blockIdx.x * blockDim.x + t;
    if (i >= n) return;
    int b = i / SCAN_B;
    int base = (b == 0) ? 0 : sb[b - 1];
    int ci = cnt[i];
    int excl = scan[i] - ci + base;
    rowptr[i] = excl;
    cursor[i] = excl;
    dinv[i] = rsqrtf((float)(ci + 1));
    if (i == n - 1) rowptr[n] = excl + ci;
}
__global__ void k_fill(const int* __restrict__ src, const int* __restrict__ dst,
                       const float* __restrict__ dinv, int* cursor,
                       int2* __restrict__ csr, int e) {
    int i = blockIdx.x * blockDim.x + threadIdx.x;
    int base = i * 4;
    if (base + 3 < e) {
        int4 sv = *reinterpret_cast<const int4*>(src + base);
        int4 dv = *reinterpret_cast<const int4*>(dst + base);
        const int ss[4] = {sv.x, sv.y, sv.z, sv.w};
        const int dd[4] = {dv.x, dv.y, dv.z, dv.w};
#pragma unroll
        for (int j = 0; j < 4; j++) {
            int pos = atomicAdd(&cursor[dd[j]], 1);
            csr[pos] = make_int2(ss[j],
                                 __float_as_int(dinv[ss[j]] * dinv[dd[j]]));
        }
    } else {
        for (int j = base; j < e; j++) {
            int s = src[j], d = dst[j];
            int pos = atomicAdd(&cursor[d], 1);
            csr[pos] = make_int2(s, __float_as_int(dinv[s] * dinv[d]));
        }
    }
}
__global__ void k_zero(int* p, int n) {
    int i = blockIdx.x * blockDim.x + threadIdx.x;
    if (i < n) p[i] = 0;
}

// ---------------------------------------------------------------------------
// Warp-per-node aggregation (fp16 gathers) — 2-edge loop (MLP sweet spot).
// ---------------------------------------------------------------------------
__global__ void k_agg_csr128(const __half* __restrict__ h,
                             const int* __restrict__ rowptr,
                             const int2* __restrict__ csr,
                             const float* __restrict__ dinv,
                             const float* __restrict__ b1,
                             __half* __restrict__ out, int n) {
    int node = (blockIdx.x * blockDim.x + threadIdx.x) >> 5;
    int lane = threadIdx.x & 31;
    if (node >= n) return;
    float di = dinv[node];
    float c = di * di;
    uint2 raw = *reinterpret_cast<const uint2*>(h + (size_t)node * 128 + lane * 4);
    float2 p0 = __half22float2(*reinterpret_cast<const __half2*>(&raw.x));
    float2 p1 = __half22float2(*reinterpret_cast<const __half2*>(&raw.y));
    float4 acc = make_float4(p0.x * c, p0.y * c, p1.x * c, p1.y * c);
    int idx = rowptr[node], end = rowptr[node + 1];
    for (; idx + 1 < end; idx += 2) {
        int2 e0 = csr[idx];
        int2 e1 = csr[idx + 1];
        float c0 = __int_as_float(e0.y);
        float c1 = __int_as_float(e1.y);
        uint2 r0 = *reinterpret_cast<const uint2*>(h + (size_t)e0.x * 128 + lane * 4);
        uint2 r1 = *reinterpret_cast<const uint2*>(h + (size_t)e1.x * 128 + lane * 4);
        float2 a0 = __half22float2(*reinterpret_cast<const __half2*>(&r0.x));
        float2 a1 = __half22float2(*reinterpret_cast<const __half2*>(&r0.y));
        float2 b0 = __half22float2(*reinterpret_cast<const __half2*>(&r1.x));
        float2 b1v = __half22float2(*reinterpret_cast<const __half2*>(&r1.y));
        acc.x = fmaf(a0.x, c0, acc.x); acc.y = fmaf(a0.y, c0, acc.y);
        acc.z = fmaf(a1.x, c0, acc.z); acc.w = fmaf(a1.y, c0, acc.w);
        acc.x = fmaf(b0.x, c1, acc.x); acc.y = fmaf(b0.y, c1, acc.y);
        acc.z = fmaf(b1v.x, c1, acc.z); acc.w = fmaf(b1v.y, c1, acc.w);
    }
    if (idx < end) {
        int2 e0 = csr[idx];
        float c0 = __int_as_float(e0.y);
        uint2 r0 = *reinterpret_cast<const uint2*>(h + (size_t)e0.x * 128 + lane * 4);
        float2 a0 = __half22float2(*reinterpret_cast<const __half2*>(&r0.x));
        float2 a1 = __half22float2(*reinterpret_cast<const __half2*>(&r0.y));
        acc.x = fmaf(a0.x, c0, acc.x); acc.y = fmaf(a0.y, c0, acc.y);
        acc.z = fmaf(a1.x, c0, acc.z); acc.w = fmaf(a1.y, c0, acc.w);
    }
    float4 b = *reinterpret_cast<const float4*>(b1 + lane * 4);
    __half2 o0 = __floats2half2_rn(fmaxf(acc.x + b.x, 0.f), fmaxf(acc.y + b.y, 0.f));
    __half2 o1 = __floats2half2_rn(fmaxf(acc.z + b.z, 0.f), fmaxf(acc.w + b.w, 0.f));
    uint2 o;
    o.x = *reinterpret_cast<uint32_t*>(&o0);
    o.y = *reinterpret_cast<uint32_t*>(&o1);
    *reinterpret_cast<uint2*>(out + (size_t)node * 128 + lane * 4) = o;
}

__global__ void k_agg_csr64(const __half* __restrict__ h,
                            const int* __restrict__ rowptr,
                            const int2* __restrict__ csr,
                            const float* __restrict__ dinv,
                            const float* __restrict__ bias,
                            float* __restrict__ out, int n) {
    int node = (blockIdx.x * blockDim.x + threadIdx.x) >> 5;
    int lane = threadIdx.x & 31;
    if (node >= n) return;
    float di = dinv[node];
    float c = di * di;
    uint32_t raw = *reinterpret_cast<const uint32_t*>(h + (size_t)node * 64 + lane * 2);
    float2 v = __half22float2(*reinterpret_cast<const __half2*>(&raw));
    float2 acc = make_float2(v.x * c, v.y * c);
    int idx = rowptr[node], end = rowptr[node + 1];
    for (; idx + 1 < end; idx += 2) {
        int2 e0 = csr[idx];
        int2 e1 = csr[idx + 1];
        float c0 = __int_as_float(e0.y);
        float c1 = __int_as_float(e1.y);
        uint32_t r0 = *reinterpret_cast<const uint32_t*>(h + (size_t)e0.x * 64 + lane * 2);
        uint32_t r1 = *reinterpret_cast<const uint32_t*>(h + (size_t)e1.x * 64 + lane * 2);
        float2 v0 = __half22float2(*reinterpret_cast<const __half2*>(&r0));
        float2 v1 = __half22float2(*reinterpret_cast<const __half2*>(&r1));
        acc.x = fmaf(v0.x, c0, acc.x); acc.y = fmaf(v0.y, c0, acc.y);
        acc.x = fmaf(v1.x, c1, acc.x); acc.y = fmaf(v1.y, c1, acc.y);
    }
    if (idx < end) {
        int2 e0 = csr[idx];
        float c0 = __int_as_float(e0.y);
        uint32_t r0 = *reinterpret_cast<const uint32_t*>(h + (size_t)e0.x * 64 + lane * 2);
        float2 v0 = __half22float2(*reinterpret_cast<const __half2*>(&r0));
        acc.x = fmaf(v0.x, c0, acc.x); acc.y = fmaf(v0.y, c0, acc.y);
    }
    float2 b = *reinterpret_cast<const float2*>(bias + lane * 2);
    acc.x += b.x;
    acc.y += b.y;
    *reinterpret_cast<float2*>(out + (size_t)node * 64 + lane * 2) = acc;
}

// ---------------------------------------------------------------------------
// Launch: fork CSR chain, join before agg1, SECOND join (evTail) at the end
// so all side-stream work is joined before capture ends.
// ---------------------------------------------------------------------------
extern "C" void kernel_launch(void* const* d_in, const int* in_sizes, int n_in,
                              void* d_out, int out_size) {
    const float* x = (const float*)d_in[0];
    const int* ei = (const int*)d_in[1];
    const float* W1 = (const float*)d_in[2];
    const float* b1 = (const float*)d_in[3];
    const float* W2 = (const float*)d_in[4];
    const float* b2 = (const float*)d_in[5];
    float* out = (float*)d_out;

    const int n = in_sizes[0] / IN_F;  // 100000
    const int e = in_sizes[1] / 2;     // 1600000
    const int* src = ei;
    const int* dst = ei + e;
    const int nb = (n + SCAN_B - 1) / SCAN_B;

    int *p_cnt, *p_scan, *p_bsum, *p_rowptr, *p_cursor;
    int2* p_csr;
    float* p_dinv;
    __half *p_h1, *p_agg1, *p_h2, *p_w1t, *p_w2t;
    cudaGetSymbolAddress((void**)&p_cnt, g_cnt);
    cudaGetSymbolAddress((void**)&p_scan, g_scan);
    cudaGetSymbolAddress((void**)&p_bsum, g_bsum);
    cudaGetSymbolAddress((void**)&p_rowptr, g_rowptr);
    cudaGetSymbolAddress((void**)&p_cursor, g_cursor);
    cudaGetSymbolAddress((void**)&p_csr, g_csr);
    cudaGetSymbolAddress((void**)&p_dinv, g_dinv);
    cudaGetSymbolAddress((void**)&p_h1, g_h1);
    cudaGetSymbolAddress((void**)&p_agg1, g_agg1);
    cudaGetSymbolAddress((void**)&p_h2, g_h2);
    cudaGetSymbolAddress((void**)&p_w1t, g_w1t);
    cudaGetSymbolAddress((void**)&p_w2t, g_w2t);

    static cudaStream_t s2 = nullptr;
    static cudaEvent_t evFork = nullptr, evJoin = nullptr, evTail = nullptr;
    if (s2 == nullptr) {
        cudaStreamCreateWithFlags(&s2, cudaStreamNonBlocking);
        cudaEventCreateWithFlags(&evFork, cudaEventDisableTiming);
        cudaEventCreateWithFlags(&evJoin, cudaEventDisableTiming);
        cudaEventCreateWithFlags(&evTail, cudaEventDisableTiming);
    }

    // ---- fork: CSR build + W2 transpose on side stream (cnt pre-zeroed)
    cudaEventRecord(evFork, 0);
    cudaStreamWaitEvent(s2, evFork, 0);
    k_cnt<<<(e / 4 + 255) / 256, 256, 0, s2>>>(dst, p_cnt, e);
    k_scan1<<<nb, SCAN_B, 0, s2>>>(p_cnt, p_scan, p_bsum, n);
    k_scan3<<<(n + 255) / 256, 256, 0, s2>>>(p_cnt, p_scan, p_bsum, p_rowptr,
                                             p_cursor, p_dinv, n, nb);
    k_fill<<<(e / 4 + 255) / 256, 256, 0, s2>>>(src, dst, p_dinv, p_cursor,
                                                p_csr, e);
    k_transpose_h<<<(HID * OUT_F + 255) / 256, 256, 0, s2>>>(W2, p_w2t, HID, OUT_F);
    cudaEventRecord(evJoin, s2);
    // tail: re-zero cnt for the NEXT call/replay (overlaps GEMM2/agg2)
    k_zero<<<(n + 255) / 256, 256, 0, s2>>>(p_cnt, n);
    cudaEventRecord(evTail, s2);

    // ---- main stream: W1 transpose + GEMM1
    k_transpose_h<<<(IN_F * HID + 255) / 256, 256>>>(W1, p_w1t, IN_F, HID);

    const int grid_m = (n + 127) / 128;
    {
        constexpr int SMEM1 = 3 * (128 * 96 + HID * 48);  // 55296
        cudaFuncSetAttribute(k_gemm_f32a<HID, IN_F>,
                             cudaFuncAttributeMaxDynamicSharedMemorySize, SMEM1);
        k_gemm_f32a<HID, IN_F><<<grid_m, 256, SMEM1>>>(n, x, p_w1t, p_h1);
    }

    // ---- join: aggregation needs the CSR
    cudaStreamWaitEvent(0, evJoin, 0);

    k_agg_csr128<<<(n * 32 + 255) / 256, 256>>>(p_h1, p_rowptr, p_csr, p_dinv,
                                                b1, p_agg1, n);

    {
        constexpr int SMEM2 = 3 * (128 * 48 + OUT_F * 48);  // 27648
        cudaFuncSetAttribute(k_gemm_f16a<OUT_F, HID>,
                             cudaFuncAttributeMaxDynamicSharedMemorySize, SMEM2);
        k_gemm_f16a<OUT_F, HID><<<grid_m, 256, SMEM2>>>(n, p_agg1, p_w2t, p_h2);
    }

    k_agg_csr64<<<(n * 32 + 255) / 256, 256>>>(p_h2, p_rowptr, p_csr, p_dinv,
                                               b2, out, n);

    // ---- final join: side stream fully merged before capture ends
    cudaStreamWaitEvent(0, evTail, 0);
}

// round 16
// speedup vs baseline: 1.4206x; 1.0352x over previous
#include <cuda_runtime.h>
#include <cuda_fp16.h>
#include <cuda_bf16.h>
#include <cstdint>

#define NMAX 100000
#define EMAX 1600000
#define IN_F 256
#define HID 128
#define OUT_F 64
#define SCAN_B 1024

// ---------------------------------------------------------------------------
// Scratch (bss). g_cnt: zero at load; re-zeroed by k_zero each call.
// ---------------------------------------------------------------------------
__device__ int   g_cnt[NMAX];
__device__ int   g_scan[NMAX];
__device__ int   g_bsum[(NMAX + SCAN_B - 1) / SCAN_B];
__device__ int   g_rowptr[NMAX + 1];
__device__ int   g_cursor[NMAX];
__device__ __align__(16) int g_csr[EMAX];          // src index only (4B/edge)
__device__ float g_dinv[NMAX];
__device__ __align__(128) __half g_h1[(size_t)NMAX * HID];    // dinv-scaled h1
__device__ __align__(128) __half g_agg1[(size_t)NMAX * HID];  // dinv*relu(...)
__device__ __align__(128) __half g_h2[(size_t)NMAX * OUT_F];  // pre-scaled h2
__device__ __align__(128) __half g_w1t[HID * IN_F];
__device__ __align__(128) __half g_w2t[OUT_F * HID];

// ---------------------------------------------------------------------------
// PTX helpers
// ---------------------------------------------------------------------------
__device__ __forceinline__ uint32_t smem_u32(const void* p) {
    uint32_t a;
    asm("{ .reg .u64 t; cvta.to.shared.u64 t, %1; cvt.u32.u64 %0, t; }"
        : "=r"(a) : "l"(p));
    return a;
}
__device__ __forceinline__ void cp_async16(uint32_t sa, const void* g) {
    asm volatile("cp.async.cg.shared.global [%0], [%1], 16;" ::"r"(sa), "l"(g));
}
__device__ __forceinline__ void cp_commit() {
    asm volatile("cp.async.commit_group;");
}
template <int N>
__device__ __forceinline__ void cp_wait() {
    asm volatile("cp.async.wait_group %0;" ::"n"(N));
}
__device__ __forceinline__ void ldsm_x4(uint32_t& r0, uint32_t& r1, uint32_t& r2,
                                        uint32_t& r3, uint32_t addr) {
    asm volatile("ldmatrix.sync.aligned.m8n8.x4.shared.b16 {%0,%1,%2,%3}, [%4];"
                 : "=r"(r0), "=r"(r1), "=r"(r2), "=r"(r3) : "r"(addr));
}
__device__ __forceinline__ float2 lds64(uint32_t addr) {
    float2 v;
    asm volatile("ld.shared.v2.f32 {%0,%1}, [%2];"
                 : "=f"(v.x), "=f"(v.y) : "r"(addr));
    return v;
}
__device__ __forceinline__ uint32_t pack_h2(float lo, float hi) {
    __half2 h = __floats2half2_rn(lo, hi);
    return *reinterpret_cast<uint32_t*>(&h);
}
__device__ __forceinline__ void mma_f16(float* c, const uint32_t* a,
                                        const uint32_t* b) {
    asm volatile(
        "mma.sync.aligned.m16n8k16.row.col.f32.f16.f16.f32 "
        "{%0,%1,%2,%3}, {%4,%5,%6,%7}, {%8,%9}, {%0,%1,%2,%3};"
        : "+f"(c[0]), "+f"(c[1]), "+f"(c[2]), "+f"(c[3])
        : "r"(a[0]), "r"(a[1]), "r"(a[2]), "r"(a[3]), "r"(b[0]), "r"(b[1]));
}

// ---------------------------------------------------------------------------
// GEMM1: A fp32 -> fp16 frags via LDS.64+cvt. B fp16. Epilogue scales rows
// by rowscale[] (dinv) before fp16 store.
// ---------------------------------------------------------------------------
template <int NT, int KT>
__global__ void __launch_bounds__(256)
k_gemm_f32a(int M, const float* __restrict__ A, const __half* __restrict__ BT,
            const float* __restrict__ rowscale, __half* __restrict__ C) {
    constexpr int BK = 16;
    constexpr int T = KT / BK;
    constexpr int A_STR = 96;
    constexpr int B_STR = 48;
    constexpr int A_ST = 128 * A_STR;
    constexpr int B_ST = NT * B_STR;
    constexpr int STAGE = A_ST + B_ST;
    constexpr int NFRAG = NT / 16;

    extern __shared__ __align__(16) char smem[];
    const uint32_t sb = smem_u32(smem);
    const int tid = threadIdx.x;
    const int wid = tid >> 5, lane = tid & 31;
    const int warpM = wid >> 1, warpN = wid & 1;
    const int brow = blockIdx.x * 128;

    float acc[2][NFRAG][4];
#pragma unroll
    for (int i = 0; i < 2; i++)
#pragma unroll
        for (int j = 0; j < NFRAG; j++)
#pragma unroll
            for (int q = 0; q < 4; q++) acc[i][j][q] = 0.f;

    auto prefetch = [&](int t, int s) {
        const uint32_t ao = sb + s * STAGE;
        const uint32_t bo = ao + A_ST;
#pragma unroll
        for (int i = tid; i < 128 * 4; i += 256) {
            int m = i >> 2, q = i & 3;
            int gr = brow + m;
            if (gr >= M) gr = M - 1;
            cp_async16(ao + m * A_STR + q * 16,
                       A + (size_t)gr * KT + t * BK + q * 4);
        }
#pragma unroll
        for (int i = tid; i < NT * 2; i += 256) {
            int r = i >> 1, q = i & 1;
            cp_async16(bo + r * B_STR + q * 16,
                       BT + (size_t)r * KT + t * BK + q * 8);
        }
        cp_commit();
    };

    prefetch(0, 0);
    if (T > 1) prefetch(1, 1);

    const int ti = lane >> 3, ri = lane & 7;
    const int r4 = lane >> 2, c4 = lane & 3;

    for (int t = 0; t < T; t++) {
        const int s = t % 3;
        if (t + 1 < T) cp_wait<1>(); else cp_wait<0>();
        __syncthreads();
        if (t + 2 < T) prefetch(t + 2, (t + 2) % 3);

        const uint32_t ao = sb + s * STAGE;
        const uint32_t bo = ao + A_ST;

        uint32_t af[2][4];
#pragma unroll
        for (int mf = 0; mf < 2; mf++) {
            int m0 = warpM * 32 + mf * 16 + r4;
            uint32_t b0 = ao + m0 * A_STR + c4 * 8;
            uint32_t b1 = ao + (m0 + 8) * A_STR + c4 * 8;
            float2 f00 = lds64(b0);
            float2 f10 = lds64(b1);
            float2 f01 = lds64(b0 + 32);
            float2 f11 = lds64(b1 + 32);
            af[mf][0] = pack_h2(f00.x, f00.y);
            af[mf][1] = pack_h2(f10.x, f10.y);
            af[mf][2] = pack_h2(f01.x, f01.y);
            af[mf][3] = pack_h2(f11.x, f11.y);
        }
        uint32_t bf[NFRAG][2];
#pragma unroll
        for (int fp = 0; fp < NFRAG / 2; fp++) {
            int nr = warpN * (NT / 2) + fp * 16 + (ti >> 1) * 8 + ri;
            uint32_t off = nr * B_STR + (ti & 1) * 16;
            ldsm_x4(bf[2 * fp][0], bf[2 * fp][1], bf[2 * fp + 1][0],
                    bf[2 * fp + 1][1], bo + off);
        }
#pragma unroll
        for (int mf = 0; mf < 2; mf++)
#pragma unroll
            for (int nf = 0; nf < NFRAG; nf++)
                mma_f16(acc[mf][nf], af[mf], bf[nf]);
    }

#pragma unroll
    for (int mf = 0; mf < 2; mf++) {
        int row0 = brow + warpM * 32 + mf * 16 + (lane >> 2);
        int row1 = row0 + 8;
        float s0 = (row0 < M) ? rowscale[row0] : 0.f;
        float s1 = (row1 < M) ? rowscale[row1] : 0.f;
#pragma unroll
        for (int nf = 0; nf < NFRAG; nf++) {
            int col = warpN * (NT / 2) + nf * 8 + (lane & 3) * 2;
            if (row0 < M)
                *reinterpret_cast<__half2*>(C + (size_t)row0 * NT + col) =
                    __floats2half2_rn(acc[mf][nf][0] * s0, acc[mf][nf][1] * s0);
            if (row1 < M)
                *reinterpret_cast<__half2*>(C + (size_t)row1 * NT + col) =
                    __floats2half2_rn(acc[mf][nf][2] * s1, acc[mf][nf][3] * s1);
        }
    }
}

// ---------------------------------------------------------------------------
// GEMM2: A fp16 (pre-scaled agg1), B fp16. Output inherits the row scaling.
// ---------------------------------------------------------------------------
template <int NT, int KT>
__global__ void __launch_bounds__(256)
k_gemm_f16a(int M, const __half* __restrict__ A, const __half* __restrict__ BT,
            __half* __restrict__ C) {
    constexpr int BK = 16;
    constexpr int T = KT / BK;
    constexpr int STR = 48;
    constexpr int A_ST = 128 * STR;
    constexpr int B_ST = NT * STR;
    constexpr int STAGE = A_ST + B_ST;
    constexpr int NFRAG = NT / 16;

    extern __shared__ __align__(16) char smem[];
    const uint32_t sb = smem_u32(smem);
    const int tid = threadIdx.x;
    const int wid = tid >> 5, lane = tid & 31;
    const int warpM = wid >> 1, warpN = wid & 1;
    const int brow = blockIdx.x * 128;

    float acc[2][NFRAG][4];
#pragma unroll
    for (int i = 0; i < 2; i++)
#pragma unroll
        for (int j = 0; j < NFRAG; j++)
#pragma unroll
            for (int q = 0; q < 4; q++) acc[i][j][q] = 0.f;

    auto prefetch = [&](int t, int s) {
        const uint32_t ao = sb + s * STAGE;
        const uint32_t bo = ao + A_ST;
#pragma unroll
        for (int i = tid; i < 128 * 2; i += 256) {
            int m = i >> 1, q = i & 1;
            int gr = brow + m;
            if (gr >= M) gr = M - 1;
            cp_async16(ao + m * STR + q * 16,
                       A + (size_t)gr * KT + t * BK + q * 8);
        }
#pragma unroll
        for (int i = tid; i < NT * 2; i += 256) {
            int r = i >> 1, q = i & 1;
            cp_async16(bo + r * STR + q * 16,
                       BT + (size_t)r * KT + t * BK + q * 8);
        }
        cp_commit();
    };

    prefetch(0, 0);
    if (T > 1) prefetch(1, 1);

    const int ti = lane >> 3, ri = lane & 7;

    for (int t = 0; t < T; t++) {
        const int s = t % 3;
        if (t + 1 < T) cp_wait<1>(); else cp_wait<0>();
        __syncthreads();
        if (t + 2 < T) prefetch(t + 2, (t + 2) % 3);

        const uint32_t ao = sb + s * STAGE;
        const uint32_t bo = ao + A_ST;

        uint32_t af[2][4];
#pragma unroll
        for (int mf = 0; mf < 2; mf++) {
            int m = warpM * 32 + mf * 16 + (ti & 1) * 8 + ri;
            uint32_t addr = ao + m * STR + (ti >> 1) * 16;
            ldsm_x4(af[mf][0], af[mf][1], af[mf][2], af[mf][3], addr);
        }
        uint32_t bf[NFRAG][2];
#pragma unroll
        for (int fp = 0; fp < NFRAG / 2; fp++) {
            int nr = warpN * (NT / 2) + fp * 16 + (ti >> 1) * 8 + ri;
            uint32_t off = nr * STR + (ti & 1) * 16;
            ldsm_x4(bf[2 * fp][0], bf[2 * fp][1], bf[2 * fp + 1][0],
                    bf[2 * fp + 1][1], bo + off);
        }
#pragma unroll
        for (int mf = 0; mf < 2; mf++)
#pragma unroll
            for (int nf = 0; nf < NFRAG; nf++)
                mma_f16(acc[mf][nf], af[mf], bf[nf]);
    }

#pragma unroll
    for (int mf = 0; mf < 2; mf++) {
        int row0 = brow + warpM * 32 + mf * 16 + (lane >> 2);
        int row1 = row0 + 8;
#pragma unroll
        for (int nf = 0; nf < NFRAG; nf++) {
            int col = warpN * (NT / 2) + nf * 8 + (lane & 3) * 2;
            if (row0 < M)
                *reinterpret_cast<__half2*>(C + (size_t)row0 * NT + col) =
                    __floats2half2_rn(acc[mf][nf][0], acc[mf][nf][1]);
            if (row1 < M)
                *reinterpret_cast<__half2*>(C + (size_t)row1 * NT + col) =
                    __floats2half2_rn(acc[mf][nf][2], acc[mf][nf][3]);
        }
    }
}

// ---------------------------------------------------------------------------
// Weight transpose -> fp16
// ---------------------------------------------------------------------------
__global__ void k_transpose_h(const float* __restrict__ W,
                              __half* __restrict__ WT, int K, int N) {
    int i = blockIdx.x * blockDim.x + threadIdx.x;
    if (i >= K * N) return;
    int k = i / N, nn = i % N;
    WT[(size_t)nn * K + k] = __float2half_rn(W[i]);
}

// ---------------------------------------------------------------------------
// CSR build: cnt -> scan1 -> scan3(fused +dinv) -> fill (src-only, no coef)
// ---------------------------------------------------------------------------
__global__ void k_cnt(const int* __restrict__ dst, int* cnt, int e) {
    int i = blockIdx.x * blockDim.x + threadIdx.x;
    int base = i * 4;
    if (base + 3 < e) {
        int4 d = *reinterpret_cast<const int4*>(dst + base);
        atomicAdd(&cnt[d.x], 1);
        atomicAdd(&cnt[d.y], 1);
        atomicAdd(&cnt[d.z], 1);
        atomicAdd(&cnt[d.w], 1);
    } else {
        for (int j = base; j < e; j++) atomicAdd(&cnt[dst[j]], 1);
    }
}
__global__ void k_scan1(const int* __restrict__ cnt, int* scan, int* bsum, int n) {
    __shared__ int sh[SCAN_B];
    int i = blockIdx.x * SCAN_B + threadIdx.x;
    int v = (i < n) ? cnt[i] : 0;
    sh[threadIdx.x] = v;
    __syncthreads();
#pragma unroll
    for (int off = 1; off < SCAN_B; off <<= 1) {
        int t = (threadIdx.x >= off) ? sh[threadIdx.x - off] : 0;
        __syncthreads();
        sh[threadIdx.x] += t;
        __syncthreads();
    }
    if (i < n) scan[i] = sh[threadIdx.x];
    if (threadIdx.x == SCAN_B - 1) bsum[blockIdx.x] = sh[SCAN_B - 1];
}
__global__ void k_scan3(const int* __restrict__ cnt, const int* __restrict__ scan,
                        const int* __restrict__ bsum, int* rowptr, int* cursor,
                        float* dinv, int n, int nb) {
    __shared__ int sb[128];
    int t = threadIdx.x;
    if (t < 128) sb[t] = (t < nb) ? bsum[t] : 0;
    __syncthreads();
#pragma unroll
    for (int off = 1; off < 128; off <<= 1) {
        int tmp = (t < 128 && t >= off) ? sb[t - off] : 0;
        __syncthreads();
        if (t < 128) sb[t] += tmp;
        __syncthreads();
    }
    int i = blockIdx.x * blockDim.x + t;
    if (i >= n) return;
    int b = i / SCAN_B;
    int base = (b == 0) ? 0 : sb[b - 1];
    int ci = cnt[i];
    int excl = scan[i] - ci + base;
    rowptr[i] = excl;
    cursor[i] = excl;
    dinv[i] = rsqrtf((float)(ci + 1));
    if (i == n - 1) rowptr[n] = excl + ci;
}
__global__ void k_fill(const int* __restrict__ src, const int* __restrict__ dst,
                       int* cursor, int* __restrict__ csr, int e) {
    int i = blockIdx.x * blockDim.x + threadIdx.x;
    int base = i * 4;
    if (base + 3 < e) {
        int4 sv = *reinterpret_cast<const int4*>(src + base);
        int4 dv = *reinterpret_cast<const int4*>(dst + base);
        const int ss[4] = {sv.x, sv.y, sv.z, sv.w};
        const int dd[4] = {dv.x, dv.y, dv.z, dv.w};
#pragma unroll
        for (int j = 0; j < 4; j++) {
            int pos = atomicAdd(&cursor[dd[j]], 1);
            csr[pos] = ss[j];
        }
    } else {
        for (int j = base; j < e; j++) {
            int pos = atomicAdd(&cursor[dst[j]], 1);
            csr[pos] = src[j];
        }
    }
}
__global__ void k_zero(int* p, int n) {
    int i = blockIdx.x * blockDim.x + threadIdx.x;
    if (i < n) p[i] = 0;
}

// ---------------------------------------------------------------------------
// Aggregation: pure unweighted sums of pre-scaled rows.
// agg1: out = dinv[d] * relu(dinv[d]*sum + b1)   (fp16, GEMM2-ready)
// agg2: out = dinv[d]*sum + b2                    (fp32 final)
// ---------------------------------------------------------------------------
__global__ void k_agg_csr128(const __half* __restrict__ h,
                             const int* __restrict__ rowptr,
                             const int* __restrict__ csr,
                             const float* __restrict__ dinv,
                             const float* __restrict__ b1,
                             __half* __restrict__ out, int n) {
    int node = (blockIdx.x * blockDim.x + threadIdx.x) >> 5;
    int lane = threadIdx.x & 31;
    if (node >= n) return;
    float di = dinv[node];
    uint2 raw = *reinterpret_cast<const uint2*>(h + (size_t)node * 128 + lane * 4);
    float2 p0 = __half22float2(*reinterpret_cast<const __half2*>(&raw.x));
    float2 p1 = __half22float2(*reinterpret_cast<const __half2*>(&raw.y));
    float4 acc = make_float4(p0.x, p0.y, p1.x, p1.y);
    int idx = rowptr[node], end = rowptr[node + 1];
    for (; idx + 1 < end; idx += 2) {
        int s0 = csr[idx];
        int s1 = csr[idx + 1];
        uint2 r0 = *reinterpret_cast<const uint2*>(h + (size_t)s0 * 128 + lane * 4);
        uint2 r1 = *reinterpret_cast<const uint2*>(h + (size_t)s1 * 128 + lane * 4);
        float2 a0 = __half22float2(*reinterpret_cast<const __half2*>(&r0.x));
        float2 a1 = __half22float2(*reinterpret_cast<const __half2*>(&r0.y));
        float2 b0 = __half22float2(*reinterpret_cast<const __half2*>(&r1.x));
        float2 b1v = __half22float2(*reinterpret_cast<const __half2*>(&r1.y));
        acc.x += a0.x + b0.x;
        acc.y += a0.y + b0.y;
        acc.z += a1.x + b1v.x;
        acc.w += a1.y + b1v.y;
    }
    if (idx < end) {
        int s0 = csr[idx];
        uint2 r0 = *reinterpret_cast<const uint2*>(h + (size_t)s0 * 128 + lane * 4);
        float2 a0 = __half22float2(*reinterpret_cast<const __half2*>(&r0.x));
        float2 a1 = __half22float2(*reinterpret_cast<const __half2*>(&r0.y));
        acc.x += a0.x;
        acc.y += a0.y;
        acc.z += a1.x;
        acc.w += a1.y;
    }
    float4 b = *reinterpret_cast<const float4*>(b1 + lane * 4);
    float v0 = fmaxf(fmaf(acc.x, di, b.x), 0.f) * di;
    float v1 = fmaxf(fmaf(acc.y, di, b.y), 0.f) * di;
    float v2 = fmaxf(fmaf(acc.z, di, b.z), 0.f) * di;
    float v3 = fmaxf(fmaf(acc.w, di, b.w), 0.f) * di;
    __half2 o0 = __floats2half2_rn(v0, v1);
    __half2 o1 = __floats2half2_rn(v2, v3);
    uint2 o;
    o.x = *reinterpret_cast<uint32_t*>(&o0);
    o.y = *reinterpret_cast<uint32_t*>(&o1);
    *reinterpret_cast<uint2*>(out + (size_t)node * 128 + lane * 4) = o;
}

__global__ void k_agg_csr64(const __half* __restrict__ h,
                            const int* __restrict__ rowptr,
                            const int* __restrict__ csr,
                            const float* __restrict__ dinv,
                            const float* __restrict__ bias,
                            float* __restrict__ out, int n) {
    int node = (blockIdx.x * blockDim.x + threadIdx.x) >> 5;
    int lane = threadIdx.x & 31;
    if (node >= n) return;
    float di = dinv[node];
    uint32_t raw = *reinterpret_cast<const uint32_t*>(h + (size_t)node * 64 + lane * 2);
    float2 v = __half22float2(*reinterpret_cast<const __half2*>(&raw));
    float2 acc = make_float2(v.x, v.y);
    int idx = rowptr[node], end = rowptr[node + 1];
    for (; idx + 1 < end; idx += 2) {
        int s0 = csr[idx];
        int s1 = csr[idx + 1];
        uint32_t r0 = *reinterpret_cast<const uint32_t*>(h + (size_t)s0 * 64 + lane * 2);
        uint32_t r1 = *reinterpret_cast<const uint32_t*>(h + (size_t)s1 * 64 + lane * 2);
        float2 v0 = __half22float2(*reinterpret_cast<const __half2*>(&r0));
        float2 v1 = __half22float2(*reinterpret_cast<const __half2*>(&r1));
        acc.x += v0.x + v1.x;
        acc.y += v0.y + v1.y;
    }
    if (idx < end) {
        int s0 = csr[idx];
        uint32_t r0 = *reinterpret_cast<const uint32_t*>(h + (size_t)s0 * 64 + lane * 2);
        float2 v0 = __half22float2(*reinterpret_cast<const __half2*>(&r0));
        acc.x += v0.x;
        acc.y += v0.y;
    }
    float2 b = *reinterpret_cast<const float2*>(bias + lane * 2);
    out[(size_t)node * 64 + lane * 2 + 0] = fmaf(acc.x, di, b.x);
    out[(size_t)node * 64 + lane * 2 + 1] = fmaf(acc.y, di, b.y);
}

// ---------------------------------------------------------------------------
// Launch: side chain builds dinv early (evDinv) so GEMM1 can scale rows;
// full CSR join (evJoin) before agg1; evTail joins the tail k_zero.
// ---------------------------------------------------------------------------
extern "C" void kernel_launch(void* const* d_in, const int* in_sizes, int n_in,
                              void* d_out, int out_size) {
    const float* x = (const float*)d_in[0];
    const int* ei = (const int*)d_in[1];
    const float* W1 = (const float*)d_in[2];
    const float* b1 = (const float*)d_in[3];
    const float* W2 = (const float*)d_in[4];
    const float* b2 = (const float*)d_in[5];
    float* out = (float*)d_out;

    const int n = in_sizes[0] / IN_F;  // 100000
    const int e = in_sizes[1] / 2;     // 1600000
    const int* src = ei;
    const int* dst = ei + e;
    const int nb = (n + SCAN_B - 1) / SCAN_B;

    int *p_cnt, *p_scan, *p_bsum, *p_rowptr, *p_cursor, *p_csr;
    float* p_dinv;
    __half *p_h1, *p_agg1, *p_h2, *p_w1t, *p_w2t;
    cudaGetSymbolAddress((void**)&p_cnt, g_cnt);
    cudaGetSymbolAddress((void**)&p_scan, g_scan);
    cudaGetSymbolAddress((void**)&p_bsum, g_bsum);
    cudaGetSymbolAddress((void**)&p_rowptr, g_rowptr);
    cudaGetSymbolAddress((void**)&p_cursor, g_cursor);
    cudaGetSymbolAddress((void**)&p_csr, g_csr);
    cudaGetSymbolAddress((void**)&p_dinv, g_dinv);
    cudaGetSymbolAddress((void**)&p_h1, g_h1);
    cudaGetSymbolAddress((void**)&p_agg1, g_agg1);
    cudaGetSymbolAddress((void**)&p_h2, g_h2);
    cudaGetSymbolAddress((void**)&p_w1t, g_w1t);
    cudaGetSymbolAddress((void**)&p_w2t, g_w2t);

    static cudaStream_t s2 = nullptr;
    static cudaEvent_t evFork = nullptr, evDinv = nullptr, evJoin = nullptr,
                       evTail = nullptr;
    if (s2 == nullptr) {
        cudaStreamCreateWithFlags(&s2, cudaStreamNonBlocking);
        cudaEventCreateWithFlags(&evFork, cudaEventDisableTiming);
        cudaEventCreateWithFlags(&evDinv, cudaEventDisableTiming);
        cudaEventCreateWithFlags(&evJoin, cudaEventDisableTiming);
        cudaEventCreateWithFlags(&evTail, cudaEventDisableTiming);
    }

    // ---- fork: CSR build on side stream (cnt pre-zeroed)
    cudaEventRecord(evFork, 0);
    cudaStreamWaitEvent(s2, evFork, 0);
    k_cnt<<<(e / 4 + 255) / 256, 256, 0, s2>>>(dst, p_cnt, e);
    k_scan1<<<nb, SCAN_B, 0, s2>>>(p_cnt, p_scan, p_bsum, n);
    k_scan3<<<(n + 255) / 256, 256, 0, s2>>>(p_cnt, p_scan, p_bsum, p_rowptr,
                                             p_cursor, p_dinv, n, nb);
    cudaEventRecord(evDinv, s2);  // dinv ready for GEMM1 epilogue
    k_fill<<<(e / 4 + 255) / 256, 256, 0, s2>>>(src, dst, p_cursor, p_csr, e);
    k_transpose_h<<<(HID * OUT_F + 255) / 256, 256, 0, s2>>>(W2, p_w2t, HID, OUT_F);
    cudaEventRecord(evJoin, s2);
    k_zero<<<(n + 255) / 256, 256, 0, s2>>>(p_cnt, n);  // for next replay
    cudaEventRecord(evTail, s2);

    // ---- main stream: W1 transpose, wait dinv, GEMM1 (scaled epilogue)
    k_transpose_h<<<(IN_F * HID + 255) / 256, 256>>>(W1, p_w1t, IN_F, HID);
    cudaStreamWaitEvent(0, evDinv, 0);

    const int grid_m = (n + 127) / 128;
    {
        constexpr int SMEM1 = 3 * (128 * 96 + HID * 48);  // 55296
        cudaFuncSetAttribute(k_gemm_f32a<HID, IN_F>,
                             cudaFuncAttributeMaxDynamicSharedMemorySize, SMEM1);
        k_gemm_f32a<HID, IN_F><<<grid_m, 256, SMEM1>>>(n, x, p_w1t, p_dinv, p_h1);
    }

    // ---- join: aggregation needs the full CSR
    cudaStreamWaitEvent(0, evJoin, 0);

    k_agg_csr128<<<(n * 32 + 255) / 256, 256>>>(p_h1, p_rowptr, p_csr, p_dinv,
                                                b1, p_agg1, n);

    {
        constexpr int SMEM2 = 3 * (128 * 48 + OUT_F * 48);  // 27648
        cudaFuncSetAttribute(k_gemm_f16a<OUT_F, HID>,
                             cudaFuncAttributeMaxDynamicSharedMemorySize, SMEM2);
        k_gemm_f16a<OUT_F, HID><<<grid_m, 256, SMEM2>>>(n, p_agg1, p_w2t, p_h2);
    }

    k_agg_csr64<<<(n * 32 + 255) / 256, 256>>>(p_h2, p_rowptr, p_csr, p_dinv,
                                               b2, out, n);

    // ---- final join: side stream fully merged before capture ends
    cudaStreamWaitEvent(0, evTail, 0);
}

// round 17
// speedup vs baseline: 1.4369x; 1.0115x over previous
#include <cuda_runtime.h>
#include <cuda_fp16.h>
#include <cuda_bf16.h>
#include <cstdint>

#define NMAX 100000
#define EMAX 1600000
#define IN_F 256
#define HID 128
#define OUT_F 64
#define SCAN_B 1024

// ---------------------------------------------------------------------------
// Scratch (bss). g_cnt: zero at load; re-zeroed by k_zero each call.
// ---------------------------------------------------------------------------
__device__ int   g_cnt[NMAX];
__device__ int   g_scan[NMAX];
__device__ int   g_bsum[(NMAX + SCAN_B - 1) / SCAN_B];
__device__ int   g_rowptr[NMAX + 1];
__device__ int   g_cursor[NMAX];
__device__ __align__(16) int g_csr[EMAX];          // src index only (4B/edge)
__device__ float g_dinv[NMAX];
__device__ __align__(128) __half g_h1[(size_t)NMAX * HID];    // dinv-scaled h1
__device__ __align__(128) __half g_agg1[(size_t)NMAX * HID];  // dinv*relu(...)
__device__ __align__(128) __half g_h2[(size_t)NMAX * OUT_F];  // pre-scaled h2
__device__ __align__(128) __half g_w1t[HID * IN_F];
__device__ __align__(128) __half g_w2t[OUT_F * HID];

// ---------------------------------------------------------------------------
// PTX helpers
// ---------------------------------------------------------------------------
__device__ __forceinline__ uint32_t smem_u32(const void* p) {
    uint32_t a;
    asm("{ .reg .u64 t; cvta.to.shared.u64 t, %1; cvt.u32.u64 %0, t; }"
        : "=r"(a) : "l"(p));
    return a;
}
__device__ __forceinline__ void cp_async16(uint32_t sa, const void* g) {
    asm volatile("cp.async.cg.shared.global [%0], [%1], 16;" ::"r"(sa), "l"(g));
}
__device__ __forceinline__ void cp_commit() {
    asm volatile("cp.async.commit_group;");
}
template <int N>
__device__ __forceinline__ void cp_wait() {
    asm volatile("cp.async.wait_group %0;" ::"n"(N));
}
__device__ __forceinline__ void ldsm_x4(uint32_t& r0, uint32_t& r1, uint32_t& r2,
                                        uint32_t& r3, uint32_t addr) {
    asm volatile("ldmatrix.sync.aligned.m8n8.x4.shared.b16 {%0,%1,%2,%3}, [%4];"
                 : "=r"(r0), "=r"(r1), "=r"(r2), "=r"(r3) : "r"(addr));
}
__device__ __forceinline__ float2 lds64(uint32_t addr) {
    float2 v;
    asm volatile("ld.shared.v2.f32 {%0,%1}, [%2];"
                 : "=f"(v.x), "=f"(v.y) : "r"(addr));
    return v;
}
__device__ __forceinline__ uint32_t pack_h2(float lo, float hi) {
    __half2 h = __floats2half2_rn(lo, hi);
    return *reinterpret_cast<uint32_t*>(&h);
}
__device__ __forceinline__ void mma_f16(float* c, const uint32_t* a,
                                        const uint32_t* b) {
    asm volatile(
        "mma.sync.aligned.m16n8k16.row.col.f32.f16.f16.f32 "
        "{%0,%1,%2,%3}, {%4,%5,%6,%7}, {%8,%9}, {%0,%1,%2,%3};"
        : "+f"(c[0]), "+f"(c[1]), "+f"(c[2]), "+f"(c[3])
        : "r"(a[0]), "r"(a[1]), "r"(a[2]), "r"(a[3]), "r"(b[0]), "r"(b[1]));
}

// ---------------------------------------------------------------------------
// GEMM1: A fp32 -> fp16 frags via LDS.64+cvt. B fp16. Row-scaled epilogue.
// ---------------------------------------------------------------------------
template <int NT, int KT>
__global__ void __launch_bounds__(256)
k_gemm_f32a(int M, const float* __restrict__ A, const __half* __restrict__ BT,
            const float* __restrict__ rowscale, __half* __restrict__ C) {
    constexpr int BK = 16;
    constexpr int T = KT / BK;
    constexpr int A_STR = 96;
    constexpr int B_STR = 48;
    constexpr int A_ST = 128 * A_STR;
    constexpr int B_ST = NT * B_STR;
    constexpr int STAGE = A_ST + B_ST;
    constexpr int NFRAG = NT / 16;

    extern __shared__ __align__(16) char smem[];
    const uint32_t sb = smem_u32(smem);
    const int tid = threadIdx.x;
    const int wid = tid >> 5, lane = tid & 31;
    const int warpM = wid >> 1, warpN = wid & 1;
    const int brow = blockIdx.x * 128;

    float acc[2][NFRAG][4];
#pragma unroll
    for (int i = 0; i < 2; i++)
#pragma unroll
        for (int j = 0; j < NFRAG; j++)
#pragma unroll
            for (int q = 0; q < 4; q++) acc[i][j][q] = 0.f;

    auto prefetch = [&](int t, int s) {
        const uint32_t ao = sb + s * STAGE;
        const uint32_t bo = ao + A_ST;
#pragma unroll
        for (int i = tid; i < 128 * 4; i += 256) {
            int m = i >> 2, q = i & 3;
            int gr = brow + m;
            if (gr >= M) gr = M - 1;
            cp_async16(ao + m * A_STR + q * 16,
                       A + (size_t)gr * KT + t * BK + q * 4);
        }
#pragma unroll
        for (int i = tid; i < NT * 2; i += 256) {
            int r = i >> 1, q = i & 1;
            cp_async16(bo + r * B_STR + q * 16,
                       BT + (size_t)r * KT + t * BK + q * 8);
        }
        cp_commit();
    };

    prefetch(0, 0);
    if (T > 1) prefetch(1, 1);

    const int ti = lane >> 3, ri = lane & 7;
    const int r4 = lane >> 2, c4 = lane & 3;

    for (int t = 0; t < T; t++) {
        const int s = t % 3;
        if (t + 1 < T) cp_wait<1>(); else cp_wait<0>();
        __syncthreads();
        if (t + 2 < T) prefetch(t + 2, (t + 2) % 3);

        const uint32_t ao = sb + s * STAGE;
        const uint32_t bo = ao + A_ST;

        uint32_t af[2][4];
#pragma unroll
        for (int mf = 0; mf < 2; mf++) {
            int m0 = warpM * 32 + mf * 16 + r4;
            uint32_t b0 = ao + m0 * A_STR + c4 * 8;
            uint32_t b1 = ao + (m0 + 8) * A_STR + c4 * 8;
            float2 f00 = lds64(b0);
            float2 f10 = lds64(b1);
            float2 f01 = lds64(b0 + 32);
            float2 f11 = lds64(b1 + 32);
            af[mf][0] = pack_h2(f00.x, f00.y);
            af[mf][1] = pack_h2(f10.x, f10.y);
            af[mf][2] = pack_h2(f01.x, f01.y);
            af[mf][3] = pack_h2(f11.x, f11.y);
        }
        uint32_t bf[NFRAG][2];
#pragma unroll
        for (int fp = 0; fp < NFRAG / 2; fp++) {
            int nr = warpN * (NT / 2) + fp * 16 + (ti >> 1) * 8 + ri;
            uint32_t off = nr * B_STR + (ti & 1) * 16;
            ldsm_x4(bf[2 * fp][0], bf[2 * fp][1], bf[2 * fp + 1][0],
                    bf[2 * fp + 1][1], bo + off);
        }
#pragma unroll
        for (int mf = 0; mf < 2; mf++)
#pragma unroll
            for (int nf = 0; nf < NFRAG; nf++)
                mma_f16(acc[mf][nf], af[mf], bf[nf]);
    }

#pragma unroll
    for (int mf = 0; mf < 2; mf++) {
        int row0 = brow + warpM * 32 + mf * 16 + (lane >> 2);
        int row1 = row0 + 8;
        float s0 = (row0 < M) ? rowscale[row0] : 0.f;
        float s1 = (row1 < M) ? rowscale[row1] : 0.f;
#pragma unroll
        for (int nf = 0; nf < NFRAG; nf++) {
            int col = warpN * (NT / 2) + nf * 8 + (lane & 3) * 2;
            if (row0 < M)
                *reinterpret_cast<__half2*>(C + (size_t)row0 * NT + col) =
                    __floats2half2_rn(acc[mf][nf][0] * s0, acc[mf][nf][1] * s0);
            if (row1 < M)
                *reinterpret_cast<__half2*>(C + (size_t)row1 * NT + col) =
                    __floats2half2_rn(acc[mf][nf][2] * s1, acc[mf][nf][3] * s1);
        }
    }
}

// ---------------------------------------------------------------------------
// GEMM2: A fp16 (pre-scaled agg1), B fp16.
// ---------------------------------------------------------------------------
template <int NT, int KT>
__global__ void __launch_bounds__(256)
k_gemm_f16a(int M, const __half* __restrict__ A, const __half* __restrict__ BT,
            __half* __restrict__ C) {
    constexpr int BK = 16;
    constexpr int T = KT / BK;
    constexpr int STR = 48;
    constexpr int A_ST = 128 * STR;
    constexpr int B_ST = NT * STR;
    constexpr int STAGE = A_ST + B_ST;
    constexpr int NFRAG = NT / 16;

    extern __shared__ __align__(16) char smem[];
    const uint32_t sb = smem_u32(smem);
    const int tid = threadIdx.x;
    const int wid = tid >> 5, lane = tid & 31;
    const int warpM = wid >> 1, warpN = wid & 1;
    const int brow = blockIdx.x * 128;

    float acc[2][NFRAG][4];
#pragma unroll
    for (int i = 0; i < 2; i++)
#pragma unroll
        for (int j = 0; j < NFRAG; j++)
#pragma unroll
            for (int q = 0; q < 4; q++) acc[i][j][q] = 0.f;

    auto prefetch = [&](int t, int s) {
        const uint32_t ao = sb + s * STAGE;
        const uint32_t bo = ao + A_ST;
#pragma unroll
        for (int i = tid; i < 128 * 2; i += 256) {
            int m = i >> 1, q = i & 1;
            int gr = brow + m;
            if (gr >= M) gr = M - 1;
            cp_async16(ao + m * STR + q * 16,
                       A + (size_t)gr * KT + t * BK + q * 8);
        }
#pragma unroll
        for (int i = tid; i < NT * 2; i += 256) {
            int r = i >> 1, q = i & 1;
            cp_async16(bo + r * STR + q * 16,
                       BT + (size_t)r * KT + t * BK + q * 8);
        }
        cp_commit();
    };

    prefetch(0, 0);
    if (T > 1) prefetch(1, 1);

    const int ti = lane >> 3, ri = lane & 7;

    for (int t = 0; t < T; t++) {
        const int s = t % 3;
        if (t + 1 < T) cp_wait<1>(); else cp_wait<0>();
        __syncthreads();
        if (t + 2 < T) prefetch(t + 2, (t + 2) % 3);

        const uint32_t ao = sb + s * STAGE;
        const uint32_t bo = ao + A_ST;

        uint32_t af[2][4];
#pragma unroll
        for (int mf = 0; mf < 2; mf++) {
            int m = warpM * 32 + mf * 16 + (ti & 1) * 8 + ri;
            uint32_t addr = ao + m * STR + (ti >> 1) * 16;
            ldsm_x4(af[mf][0], af[mf][1], af[mf][2], af[mf][3], addr);
        }
        uint32_t bf[NFRAG][2];
#pragma unroll
        for (int fp = 0; fp < NFRAG / 2; fp++) {
            int nr = warpN * (NT / 2) + fp * 16 + (ti >> 1) * 8 + ri;
            uint32_t off = nr * STR + (ti & 1) * 16;
            ldsm_x4(bf[2 * fp][0], bf[2 * fp][1], bf[2 * fp + 1][0],
                    bf[2 * fp + 1][1], bo + off);
        }
#pragma unroll
        for (int mf = 0; mf < 2; mf++)
#pragma unroll
            for (int nf = 0; nf < NFRAG; nf++)
                mma_f16(acc[mf][nf], af[mf], bf[nf]);
    }

#pragma unroll
    for (int mf = 0; mf < 2; mf++) {
        int row0 = brow + warpM * 32 + mf * 16 + (lane >> 2);
        int row1 = row0 + 8;
#pragma unroll
        for (int nf = 0; nf < NFRAG; nf++) {
            int col = warpN * (NT / 2) + nf * 8 + (lane & 3) * 2;
            if (row0 < M)
                *reinterpret_cast<__half2*>(C + (size_t)row0 * NT + col) =
                    __floats2half2_rn(acc[mf][nf][0], acc[mf][nf][1]);
            if (row1 < M)
                *reinterpret_cast<__half2*>(C + (size_t)row1 * NT + col) =
                    __floats2half2_rn(acc[mf][nf][2], acc[mf][nf][3]);
        }
    }
}

// ---------------------------------------------------------------------------
// Weight transpose -> fp16
// ---------------------------------------------------------------------------
__global__ void k_transpose_h(const float* __restrict__ W,
                              __half* __restrict__ WT, int K, int N) {
    int i = blockIdx.x * blockDim.x + threadIdx.x;
    if (i >= K * N) return;
    int k = i / N, nn = i % N;
    WT[(size_t)nn * K + k] = __float2half_rn(W[i]);
}

// ---------------------------------------------------------------------------
// CSR build: cnt (main stream) -> [fork] scan1 -> scan3(+dinv) -> fill
// ---------------------------------------------------------------------------
__global__ void k_cnt(const int* __restrict__ dst, int* cnt, int e) {
    int i = blockIdx.x * blockDim.x + threadIdx.x;
    int base = i * 4;
    if (base + 3 < e) {
        int4 d = *reinterpret_cast<const int4*>(dst + base);
        atomicAdd(&cnt[d.x], 1);
        atomicAdd(&cnt[d.y], 1);
        atomicAdd(&cnt[d.z], 1);
        atomicAdd(&cnt[d.w], 1);
    } else {
        for (int j = base; j < e; j++) atomicAdd(&cnt[dst[j]], 1);
    }
}
__global__ void k_scan1(const int* __restrict__ cnt, int* scan, int* bsum, int n) {
    __shared__ int sh[SCAN_B];
    int i = blockIdx.x * SCAN_B + threadIdx.x;
    int v = (i < n) ? cnt[i] : 0;
    sh[threadIdx.x] = v;
    __syncthreads();
#pragma unroll
    for (int off = 1; off < SCAN_B; off <<= 1) {
        int t = (threadIdx.x >= off) ? sh[threadIdx.x - off] : 0;
        __syncthreads();
        sh[threadIdx.x] += t;
        __syncthreads();
    }
    if (i < n) scan[i] = sh[threadIdx.x];
    if (threadIdx.x == SCAN_B - 1) bsum[blockIdx.x] = sh[SCAN_B - 1];
}
__global__ void k_scan3(const int* __restrict__ cnt, const int* __restrict__ scan,
                        const int* __restrict__ bsum, int* rowptr, int* cursor,
                        float* dinv, int n, int nb) {
    __shared__ int sb[128];
    int t = threadIdx.x;
    if (t < 128) sb[t] = (t < nb) ? bsum[t] : 0;
    __syncthreads();
#pragma unroll
    for (int off = 1; off < 128; off <<= 1) {
        int tmp = (t < 128 && t >= off) ? sb[t - off] : 0;
        __syncthreads();
        if (t < 128) sb[t] += tmp;
        __syncthreads();
    }
    int i = blockIdx.x * blockDim.x + t;
    if (i >= n) return;
    int b = i / SCAN_B;
    int base = (b == 0) ? 0 : sb[b - 1];
    int ci = cnt[i];
    int excl = scan[i] - ci + base;
    rowptr[i] = excl;
    cursor[i] = excl;
    dinv[i] = rsqrtf((float)(ci + 1));
    if (i == n - 1) rowptr[n] = excl + ci;
}
__global__ void k_fill(const int* __restrict__ src, const int* __restrict__ dst,
                       int* cursor, int* __restrict__ csr, int e) {
    int i = blockIdx.x * blockDim.x + threadIdx.x;
    int base = i * 4;
    if (base + 3 < e) {
        int4 sv = *reinterpret_cast<const int4*>(src + base);
        int4 dv = *reinterpret_cast<const int4*>(dst + base);
        const int ss[4] = {sv.x, sv.y, sv.z, sv.w};
        const int dd[4] = {dv.x, dv.y, dv.z, dv.w};
#pragma unroll
        for (int j = 0; j < 4; j++) {
            int pos = atomicAdd(&cursor[dd[j]], 1);
            csr[pos] = ss[j];
        }
    } else {
        for (int j = base; j < e; j++) {
            int pos = atomicAdd(&cursor[dst[j]], 1);
            csr[pos] = src[j];
        }
    }
}
__global__ void k_zero(int* p, int n) {
    int i = blockIdx.x * blockDim.x + threadIdx.x;
    if (i < n) p[i] = 0;
}

// ---------------------------------------------------------------------------
// Aggregation: pure unweighted sums of pre-scaled rows.
// ---------------------------------------------------------------------------
__global__ void k_agg_csr128(const __half* __restrict__ h,
                             const int* __restrict__ rowptr,
                             const int* __restrict__ csr,
                             const float* __restrict__ dinv,
                             const float* __restrict__ b1,
                             __half* __restrict__ out, int n) {
    int node = (blockIdx.x * blockDim.x + threadIdx.x) >> 5;
    int lane = threadIdx.x & 31;
    if (node >= n) return;
    float di = dinv[node];
    uint2 raw = *reinterpret_cast<const uint2*>(h + (size_t)node * 128 + lane * 4);
    float2 p0 = __half22float2(*reinterpret_cast<const __half2*>(&raw.x));
    float2 p1 = __half22float2(*reinterpret_cast<const __half2*>(&raw.y));
    float4 acc = make_float4(p0.x, p0.y, p1.x, p1.y);
    int idx = rowptr[node], end = rowptr[node + 1];
    for (; idx + 1 < end; idx += 2) {
        int s0 = csr[idx];
        int s1 = csr[idx + 1];
        uint2 r0 = *reinterpret_cast<const uint2*>(h + (size_t)s0 * 128 + lane * 4);
        uint2 r1 = *reinterpret_cast<const uint2*>(h + (size_t)s1 * 128 + lane * 4);
        float2 a0 = __half22float2(*reinterpret_cast<const __half2*>(&r0.x));
        float2 a1 = __half22float2(*reinterpret_cast<const __half2*>(&r0.y));
        float2 b0 = __half22float2(*reinterpret_cast<const __half2*>(&r1.x));
        float2 b1v = __half22float2(*reinterpret_cast<const __half2*>(&r1.y));
        acc.x += a0.x + b0.x;
        acc.y += a0.y + b0.y;
        acc.z += a1.x + b1v.x;
        acc.w += a1.y + b1v.y;
    }
    if (idx < end) {
        int s0 = csr[idx];
        uint2 r0 = *reinterpret_cast<const uint2*>(h + (size_t)s0 * 128 + lane * 4);
        float2 a0 = __half22float2(*reinterpret_cast<const __half2*>(&r0.x));
        float2 a1 = __half22float2(*reinterpret_cast<const __half2*>(&r0.y));
        acc.x += a0.x;
        acc.y += a0.y;
        acc.z += a1.x;
        acc.w += a1.y;
    }
    float4 b = *reinterpret_cast<const float4*>(b1 + lane * 4);
    float v0 = fmaxf(fmaf(acc.x, di, b.x), 0.f) * di;
    float v1 = fmaxf(fmaf(acc.y, di, b.y), 0.f) * di;
    float v2 = fmaxf(fmaf(acc.z, di, b.z), 0.f) * di;
    float v3 = fmaxf(fmaf(acc.w, di, b.w), 0.f) * di;
    __half2 o0 = __floats2half2_rn(v0, v1);
    __half2 o1 = __floats2half2_rn(v2, v3);
    uint2 o;
    o.x = *reinterpret_cast<uint32_t*>(&o0);
    o.y = *reinterpret_cast<uint32_t*>(&o1);
    *reinterpret_cast<uint2*>(out + (size_t)node * 128 + lane * 4) = o;
}

__global__ void k_agg_csr64(const __half* __restrict__ h,
                            const int* __restrict__ rowptr,
                            const int* __restrict__ csr,
                            const float* __restrict__ dinv,
                            const float* __restrict__ bias,
                            float* __restrict__ out, int n) {
    int node = (blockIdx.x * blockDim.x + threadIdx.x) >> 5;
    int lane = threadIdx.x & 31;
    if (node >= n) return;
    float di = dinv[node];
    uint32_t raw = *reinterpret_cast<const uint32_t*>(h + (size_t)node * 64 + lane * 2);
    float2 v = __half22float2(*reinterpret_cast<const __half2*>(&raw));
    float2 acc = make_float2(v.x, v.y);
    int idx = rowptr[node], end = rowptr[node + 1];
    for (; idx + 1 < end; idx += 2) {
        int s0 = csr[idx];
        int s1 = csr[idx + 1];
        uint32_t r0 = *reinterpret_cast<const uint32_t*>(h + (size_t)s0 * 64 + lane * 2);
        uint32_t r1 = *reinterpret_cast<const uint32_t*>(h + (size_t)s1 * 64 + lane * 2);
        float2 v0 = __half22float2(*reinterpret_cast<const __half2*>(&r0));
        float2 v1 = __half22float2(*reinterpret_cast<const __half2*>(&r1));
        acc.x += v0.x + v1.x;
        acc.y += v0.y + v1.y;
    }
    if (idx < end) {
        int s0 = csr[idx];
        uint32_t r0 = *reinterpret_cast<const uint32_t*>(h + (size_t)s0 * 64 + lane * 2);
        float2 v0 = __half22float2(*reinterpret_cast<const __half2*>(&r0));
        acc.x += v0.x;
        acc.y += v0.y;
    }
    float2 b = *reinterpret_cast<const float2*>(bias + lane * 2);
    out[(size_t)node * 64 + lane * 2 + 0] = fmaf(acc.x, di, b.x);
    out[(size_t)node * 64 + lane * 2 + 1] = fmaf(acc.y, di, b.y);
}

// ---------------------------------------------------------------------------
// Launch: k_cnt runs FIRST on the main stream (no L2 contention with GEMM1,
// shortens side chain); fork scan1->scan3->fill->W2t; join before agg1.
// ---------------------------------------------------------------------------
extern "C" void kernel_launch(void* const* d_in, const int* in_sizes, int n_in,
                              void* d_out, int out_size) {
    const float* x = (const float*)d_in[0];
    const int* ei = (const int*)d_in[1];
    const float* W1 = (const float*)d_in[2];
    const float* b1 = (const float*)d_in[3];
    const float* W2 = (const float*)d_in[4];
    const float* b2 = (const float*)d_in[5];
    float* out = (float*)d_out;

    const int n = in_sizes[0] / IN_F;  // 100000
    const int e = in_sizes[1] / 2;     // 1600000
    const int* src = ei;
    const int* dst = ei + e;
    const int nb = (n + SCAN_B - 1) / SCAN_B;

    int *p_cnt, *p_scan, *p_bsum, *p_rowptr, *p_cursor, *p_csr;
    float* p_dinv;
    __half *p_h1, *p_agg1, *p_h2, *p_w1t, *p_w2t;
    cudaGetSymbolAddress((void**)&p_cnt, g_cnt);
    cudaGetSymbolAddress((void**)&p_scan, g_scan);
    cudaGetSymbolAddress((void**)&p_bsum, g_bsum);
    cudaGetSymbolAddress((void**)&p_rowptr, g_rowptr);
    cudaGetSymbolAddress((void**)&p_cursor, g_cursor);
    cudaGetSymbolAddress((void**)&p_csr, g_csr);
    cudaGetSymbolAddress((void**)&p_dinv, g_dinv);
    cudaGetSymbolAddress((void**)&p_h1, g_h1);
    cudaGetSymbolAddress((void**)&p_agg1, g_agg1);
    cudaGetSymbolAddress((void**)&p_h2, g_h2);
    cudaGetSymbolAddress((void**)&p_w1t, g_w1t);
    cudaGetSymbolAddress((void**)&p_w2t, g_w2t);

    static cudaStream_t s2 = nullptr;
    static cudaEvent_t evFork = nullptr, evDinv = nullptr, evJoin = nullptr,
                       evTail = nullptr;
    if (s2 == nullptr) {
        cudaStreamCreateWithFlags(&s2, cudaStreamNonBlocking);
        cudaEventCreateWithFlags(&evFork, cudaEventDisableTiming);
        cudaEventCreateWithFlags(&evDinv, cudaEventDisableTiming);
        cudaEventCreateWithFlags(&evJoin, cudaEventDisableTiming);
        cudaEventCreateWithFlags(&evTail, cudaEventDisableTiming);
    }

    // ---- main: counting pass first (cnt pre-zeroed from previous call)
    k_cnt<<<(e / 4 + 255) / 256, 256>>>(dst, p_cnt, e);
    cudaEventRecord(evFork, 0);

    // ---- side: scan chain + fill + W2 transpose
    cudaStreamWaitEvent(s2, evFork, 0);
    k_scan1<<<nb, SCAN_B, 0, s2>>>(p_cnt, p_scan, p_bsum, n);
    k_scan3<<<(n + 255) / 256, 256, 0, s2>>>(p_cnt, p_scan, p_bsum, p_rowptr,
                                             p_cursor, p_dinv, n, nb);
    cudaEventRecord(evDinv, s2);  // dinv ready for GEMM1 epilogue
    k_fill<<<(e / 4 + 255) / 256, 256, 0, s2>>>(src, dst, p_cursor, p_csr, e);
    k_transpose_h<<<(HID * OUT_F + 255) / 256, 256, 0, s2>>>(W2, p_w2t, HID, OUT_F);
    cudaEventRecord(evJoin, s2);
    k_zero<<<(n + 255) / 256, 256, 0, s2>>>(p_cnt, n);  // for next replay
    cudaEventRecord(evTail, s2);

    // ---- main: W1 transpose, wait dinv, GEMM1 (scaled epilogue)
    k_transpose_h<<<(IN_F * HID + 255) / 256, 256>>>(W1, p_w1t, IN_F, HID);
    cudaStreamWaitEvent(0, evDinv, 0);

    const int grid_m = (n + 127) / 128;
    {
        constexpr int SMEM1 = 3 * (128 * 96 + HID * 48);  // 55296
        cudaFuncSetAttribute(k_gemm_f32a<HID, IN_F>,
                             cudaFuncAttributeMaxDynamicSharedMemorySize, SMEM1);
        k_gemm_f32a<HID, IN_F><<<grid_m, 256, SMEM1>>>(n, x, p_w1t, p_dinv, p_h1);
    }

    // ---- join: aggregation needs the full CSR
    cudaStreamWaitEvent(0, evJoin, 0);

    k_agg_csr128<<<(n * 32 + 255) / 256, 256>>>(p_h1, p_rowptr, p_csr, p_dinv,
                                                b1, p_agg1, n);

    {
        constexpr int SMEM2 = 3 * (128 * 48 + OUT_F * 48);  // 27648
        cudaFuncSetAttribute(k_gemm_f16a<OUT_F, HID>,
                             cudaFuncAttributeMaxDynamicSharedMemorySize, SMEM2);
        k_gemm_f16a<OUT_F, HID><<<grid_m, 256, SMEM2>>>(n, p_agg1, p_w2t, p_h2);
    }

    k_agg_csr64<<<(n * 32 + 255) / 256, 256>>>(p_h2, p_rowptr, p_csr, p_dinv,
                                               b2, out, n);

    // ---- final join: side stream fully merged before capture ends
    cudaStreamWaitEvent(0, evTail, 0);
}